// round 1
// baseline (speedup 1.0000x reference)
#include <cuda_runtime.h>
#include <cuda_bf16.h>
#include <float.h>
#include <math.h>

// Problem constants
#define B_  2
#define S_  2048
#define E_  4096
#define HQ_ 32
#define HKV_ 8
#define D_  128
#define M_  (B_ * S_)          // 4096
#define SCALE_ 0.015625f       // 1/sqrt(4096)

// ---------------------------------------------------------------------------
// Scratch (static device globals; allocation inside kernel_launch is banned)
// ---------------------------------------------------------------------------
__device__ float g_Qp[(size_t)M_ * (HQ_ * D_)];    // 4096 x 4096  (x @ wq)
__device__ float g_Kp[(size_t)M_ * (HKV_ * D_)];   // 4096 x 1024
__device__ float g_Vp[(size_t)M_ * (HKV_ * D_)];   // 4096 x 1024
__device__ float g_Qb[(size_t)B_ * HQ_ * S_ * D_]; // roped Q  [b,h,s,d]
__device__ float g_Kc[(size_t)B_ * HKV_ * S_ * D_];// roped K  [b,h,pos,d]
__device__ float g_Vc[(size_t)B_ * HKV_ * S_ * D_];// V        [b,h,pos,d]
__device__ float g_Sc[(size_t)B_ * HQ_ * S_ * S_]; // scores   [bh, q, j]  (1.07 GB)
__device__ float g_AO[(size_t)M_ * (HQ_ * D_)];    // attn out [b*s, h*d]

// ---------------------------------------------------------------------------
// SGEMM NN: C[M,N] = A[M,K] @ B[K,N], all row-major. 128x128 tile, 256 thr,
// 8x8 micro-tile per thread, float4 vectorized. M,N multiples of 128, K of 8.
// ---------------------------------------------------------------------------
__global__ void sgemm_nn(const float* __restrict__ A, const float* __restrict__ Bm,
                         float* __restrict__ C, int M, int N, int K) {
    __shared__ float As[8][128];
    __shared__ float Bs[8][128];
    const int tid = threadIdx.x;
    const int tx = tid & 15, ty = tid >> 4;
    const int m0 = blockIdx.y * 128, n0 = blockIdx.x * 128;

    float acc[8][8] = {};

    const int a_row = tid >> 1;
    const int a_kp  = (tid & 1) * 4;
    const int b_kk  = tid >> 5;
    const int b_col = (tid & 31) * 4;

    const float* Aptr = A + (size_t)(m0 + a_row) * K + a_kp;
    const float* Bptr = Bm + (size_t)b_kk * N + n0 + b_col;

    for (int k0 = 0; k0 < K; k0 += 8) {
        float4 av = *(const float4*)(Aptr + k0);
        As[a_kp + 0][a_row] = av.x;
        As[a_kp + 1][a_row] = av.y;
        As[a_kp + 2][a_row] = av.z;
        As[a_kp + 3][a_row] = av.w;
        *(float4*)&Bs[b_kk][b_col] = *(const float4*)(Bptr + (size_t)k0 * N);
        __syncthreads();
        #pragma unroll
        for (int kk = 0; kk < 8; kk++) {
            float a[8], b[8];
            *(float4*)&a[0] = *(const float4*)&As[kk][ty * 4];
            *(float4*)&a[4] = *(const float4*)&As[kk][64 + ty * 4];
            *(float4*)&b[0] = *(const float4*)&Bs[kk][tx * 4];
            *(float4*)&b[4] = *(const float4*)&Bs[kk][64 + tx * 4];
            #pragma unroll
            for (int i = 0; i < 8; i++)
                #pragma unroll
                for (int j = 0; j < 8; j++)
                    acc[i][j] += a[i] * b[j];
        }
        __syncthreads();
    }

    #pragma unroll
    for (int i = 0; i < 8; i++) {
        int r = m0 + ((i < 4) ? (ty * 4 + i) : (64 + ty * 4 + (i - 4)));
        float* Crow = C + (size_t)r * N + n0;
        *(float4*)(Crow + tx * 4)      = make_float4(acc[i][0], acc[i][1], acc[i][2], acc[i][3]);
        *(float4*)(Crow + 64 + tx * 4) = make_float4(acc[i][4], acc[i][5], acc[i][6], acc[i][7]);
    }
}

// ---------------------------------------------------------------------------
// RoPE on Q: Qp[b*S+s, h*D + 2p..2p+1] -> Qb[((b*HQ+h)*S + s)*D + 2p..]
// ---------------------------------------------------------------------------
__global__ void rope_q_kernel(const float* __restrict__ Qp, const float* __restrict__ fc,
                              float* __restrict__ Qb) {
    int i = blockIdx.x * 256 + threadIdx.x;       // over B*S*HQ*64
    int p = i & 63;
    int h = (i >> 6) & (HQ_ - 1);
    int s = (i >> 11) & (S_ - 1);
    int b = i >> 22;
    float2 qv = ((const float2*)Qp)[((size_t)(b * S_ + s) * (HQ_ * D_) + h * D_) / 2 + p];
    float2 cs = ((const float2*)fc)[(size_t)s * 64 + p];
    float2 o;
    o.x = qv.x * cs.x - qv.y * cs.y;
    o.y = qv.x * cs.y + qv.y * cs.x;
    ((float2*)Qb)[((size_t)((b * HQ_ + h) * S_ + s) * D_) / 2 + p] = o;
}

// RoPE on K with cache scatter by input_pos
__global__ void rope_k_kernel(const float* __restrict__ Kp, const float* __restrict__ fc,
                              const int* __restrict__ input_pos, float* __restrict__ Kc) {
    int i = blockIdx.x * 256 + threadIdx.x;       // over B*S*HKV*64
    int p = i & 63;
    int h = (i >> 6) & (HKV_ - 1);
    int s = (i >> 9) & (S_ - 1);
    int b = i >> 20;
    int pos = input_pos[s];
    float2 kv = ((const float2*)Kp)[((size_t)(b * S_ + s) * (HKV_ * D_) + h * D_) / 2 + p];
    float2 cs = ((const float2*)fc)[(size_t)s * 64 + p];
    float2 o;
    o.x = kv.x * cs.x - kv.y * cs.y;
    o.y = kv.x * cs.y + kv.y * cs.x;
    ((float2*)Kc)[((size_t)((b * HKV_ + h) * S_ + pos) * D_) / 2 + p] = o;
}

// V cache scatter (no rope), float4 granularity
__global__ void copy_v_kernel(const float* __restrict__ Vp, const int* __restrict__ input_pos,
                              float* __restrict__ Vc) {
    int i = blockIdx.x * 256 + threadIdx.x;       // over B*S*HKV*32
    int c = i & 31;
    int h = (i >> 5) & (HKV_ - 1);
    int s = (i >> 8) & (S_ - 1);
    int b = i >> 19;
    int pos = input_pos[s];
    float4 v = ((const float4*)Vp)[((size_t)(b * S_ + s) * (HKV_ * D_) + h * D_) / 4 + c];
    ((float4*)Vc)[((size_t)((b * HKV_ + h) * S_ + pos) * D_) / 4 + c] = v;
}

// ---------------------------------------------------------------------------
// QK^T per (b,h): scores[bh, q, j] = scale * Q[bh,q,:] . K[b,kvh,j,:],
// causal mask (j<=q), fully-masked 128x128 blocks skipped.
// ---------------------------------------------------------------------------
__global__ void qkt_kernel(const float* __restrict__ Qb, const float* __restrict__ Kc,
                           float* __restrict__ Sc) {
    const int bh = blockIdx.z;
    const int b = bh / HQ_, h = bh % HQ_;
    const int kvh = h / (HQ_ / HKV_);
    const int tid = threadIdx.x;
    const int tx = tid & 15, ty = tid >> 4;
    const int m0 = blockIdx.y * 128, n0 = blockIdx.x * 128;

    float* Cbase = Sc + (size_t)bh * S_ * S_;

    if (n0 >= m0 + 128) {  // fully masked tile: store -FLT_MAX, no compute
        #pragma unroll
        for (int i = 0; i < 8; i++) {
            int r = m0 + ((i < 4) ? (ty * 4 + i) : (64 + ty * 4 + (i - 4)));
            float* Crow = Cbase + (size_t)r * S_ + n0;
            float4 m4 = make_float4(-FLT_MAX, -FLT_MAX, -FLT_MAX, -FLT_MAX);
            *(float4*)(Crow + tx * 4) = m4;
            *(float4*)(Crow + 64 + tx * 4) = m4;
        }
        return;
    }

    __shared__ float As[8][128];
    __shared__ float Bs[8][128];
    const float* Qbase = Qb + (size_t)(b * HQ_ + h) * S_ * D_;
    const float* Kbase = Kc + (size_t)(b * HKV_ + kvh) * S_ * D_;

    float acc[8][8] = {};
    const int l_row = tid >> 1;
    const int l_kp  = (tid & 1) * 4;
    const float* Aptr = Qbase + (size_t)(m0 + l_row) * D_ + l_kp;
    const float* Bptr = Kbase + (size_t)(n0 + l_row) * D_ + l_kp;

    for (int k0 = 0; k0 < D_; k0 += 8) {
        float4 av = *(const float4*)(Aptr + k0);
        As[l_kp + 0][l_row] = av.x;
        As[l_kp + 1][l_row] = av.y;
        As[l_kp + 2][l_row] = av.z;
        As[l_kp + 3][l_row] = av.w;
        float4 bv = *(const float4*)(Bptr + k0);
        Bs[l_kp + 0][l_row] = bv.x;
        Bs[l_kp + 1][l_row] = bv.y;
        Bs[l_kp + 2][l_row] = bv.z;
        Bs[l_kp + 3][l_row] = bv.w;
        __syncthreads();
        #pragma unroll
        for (int kk = 0; kk < 8; kk++) {
            float a[8], bb[8];
            *(float4*)&a[0]  = *(const float4*)&As[kk][ty * 4];
            *(float4*)&a[4]  = *(const float4*)&As[kk][64 + ty * 4];
            *(float4*)&bb[0] = *(const float4*)&Bs[kk][tx * 4];
            *(float4*)&bb[4] = *(const float4*)&Bs[kk][64 + tx * 4];
            #pragma unroll
            for (int i = 0; i < 8; i++)
                #pragma unroll
                for (int j = 0; j < 8; j++)
                    acc[i][j] += a[i] * bb[j];
        }
        __syncthreads();
    }

    #pragma unroll
    for (int i = 0; i < 8; i++) {
        int r = m0 + ((i < 4) ? (ty * 4 + i) : (64 + ty * 4 + (i - 4)));
        float* Crow = Cbase + (size_t)r * S_ + n0;
        float v[8];
        #pragma unroll
        for (int j = 0; j < 8; j++) {
            int c = n0 + ((j < 4) ? (tx * 4 + j) : (64 + tx * 4 + (j - 4)));
            v[j] = (c <= r) ? acc[i][j] * SCALE_ : -FLT_MAX;
        }
        *(float4*)(Crow + tx * 4)      = make_float4(v[0], v[1], v[2], v[3]);
        *(float4*)(Crow + 64 + tx * 4) = make_float4(v[4], v[5], v[6], v[7]);
    }
}

// ---------------------------------------------------------------------------
// Row softmax over scores (2048 per row), one block per row
// ---------------------------------------------------------------------------
__device__ __forceinline__ float warpMax(float v) {
    #pragma unroll
    for (int o = 16; o; o >>= 1) v = fmaxf(v, __shfl_xor_sync(0xffffffffu, v, o));
    return v;
}
__device__ __forceinline__ float warpSum(float v) {
    #pragma unroll
    for (int o = 16; o; o >>= 1) v += __shfl_xor_sync(0xffffffffu, v, o);
    return v;
}

__global__ void softmax_rows(float* __restrict__ Sc) {
    const long long row = blockIdx.x;
    float* p = Sc + row * (long long)S_;
    const int tid = threadIdx.x;
    __shared__ float sm[8], ss[8];

    float v[8];
    float m = -FLT_MAX;
    #pragma unroll
    for (int i = 0; i < 8; i++) { v[i] = p[tid + i * 256]; m = fmaxf(m, v[i]); }
    m = warpMax(m);
    if ((tid & 31) == 0) sm[tid >> 5] = m;
    __syncthreads();
    float bm = -FLT_MAX;
    #pragma unroll
    for (int i = 0; i < 8; i++) bm = fmaxf(bm, sm[i]);

    float sum = 0.f;
    #pragma unroll
    for (int i = 0; i < 8; i++) { v[i] = __expf(v[i] - bm); sum += v[i]; }
    sum = warpSum(sum);
    if ((tid & 31) == 0) ss[tid >> 5] = sum;
    __syncthreads();
    float bs = 0.f;
    #pragma unroll
    for (int i = 0; i < 8; i++) bs += ss[i];
    float inv = 1.0f / bs;
    #pragma unroll
    for (int i = 0; i < 8; i++) p[tid + i * 256] = v[i] * inv;
}

// ---------------------------------------------------------------------------
// P @ V per (b,h): AO[(b*S+q)*4096 + h*128 + d] = sum_j P[q,j] V[j,d]
// K-loop truncated at q_tile_end+1 (causal zeros beyond)
// ---------------------------------------------------------------------------
__global__ void pv_kernel(const float* __restrict__ Sc, const float* __restrict__ Vc,
                          float* __restrict__ AO) {
    const int bh = blockIdx.z;
    const int b = bh / HQ_, h = bh % HQ_;
    const int kvh = h / (HQ_ / HKV_);
    const int tid = threadIdx.x;
    const int tx = tid & 15, ty = tid >> 4;
    const int m0 = blockIdx.y * 128;

    __shared__ float As[8][128];
    __shared__ float Bs[8][128];

    const float* Pbase = Sc + (size_t)bh * S_ * S_;
    const float* Vbase = Vc + (size_t)(b * HKV_ + kvh) * S_ * D_;

    float acc[8][8] = {};
    const int a_row = tid >> 1;
    const int a_kp  = (tid & 1) * 4;
    const int b_kk  = tid >> 5;
    const int b_col = (tid & 31) * 4;

    const float* Aptr = Pbase + (size_t)(m0 + a_row) * S_ + a_kp;
    const float* Bptr = Vbase + (size_t)b_kk * D_ + b_col;

    const int kmax = m0 + 128;   // causal: keys beyond q_tile_end are zero-weight
    for (int k0 = 0; k0 < kmax; k0 += 8) {
        float4 av = *(const float4*)(Aptr + k0);
        As[a_kp + 0][a_row] = av.x;
        As[a_kp + 1][a_row] = av.y;
        As[a_kp + 2][a_row] = av.z;
        As[a_kp + 3][a_row] = av.w;
        *(float4*)&Bs[b_kk][b_col] = *(const float4*)(Bptr + (size_t)k0 * D_);
        __syncthreads();
        #pragma unroll
        for (int kk = 0; kk < 8; kk++) {
            float a[8], bb[8];
            *(float4*)&a[0]  = *(const float4*)&As[kk][ty * 4];
            *(float4*)&a[4]  = *(const float4*)&As[kk][64 + ty * 4];
            *(float4*)&bb[0] = *(const float4*)&Bs[kk][tx * 4];
            *(float4*)&bb[4] = *(const float4*)&Bs[kk][64 + tx * 4];
            #pragma unroll
            for (int i = 0; i < 8; i++)
                #pragma unroll
                for (int j = 0; j < 8; j++)
                    acc[i][j] += a[i] * bb[j];
        }
        __syncthreads();
    }

    #pragma unroll
    for (int i = 0; i < 8; i++) {
        int r = m0 + ((i < 4) ? (ty * 4 + i) : (64 + ty * 4 + (i - 4)));
        float* Crow = AO + (size_t)(b * S_ + r) * (HQ_ * D_) + h * D_;
        *(float4*)(Crow + tx * 4)      = make_float4(acc[i][0], acc[i][1], acc[i][2], acc[i][3]);
        *(float4*)(Crow + 64 + tx * 4) = make_float4(acc[i][4], acc[i][5], acc[i][6], acc[i][7]);
    }
}

// ---------------------------------------------------------------------------
// kernel_launch
// ---------------------------------------------------------------------------
extern "C" void kernel_launch(void* const* d_in, const int* in_sizes, int n_in,
                              void* d_out, int out_size) {
    const float* x   = (const float*)d_in[0];
    const int*   ip  = (const int*)  d_in[1];
    const float* fc  = (const float*)d_in[2];
    const float* wq  = (const float*)d_in[3];
    const float* wk  = (const float*)d_in[4];
    const float* wv  = (const float*)d_in[5];
    const float* wo  = (const float*)d_in[6];
    float* out = (float*)d_out;

    float *Qp, *Kp, *Vp, *Qb, *Kc, *Vc, *Sc, *AO;
    cudaGetSymbolAddress((void**)&Qp, g_Qp);
    cudaGetSymbolAddress((void**)&Kp, g_Kp);
    cudaGetSymbolAddress((void**)&Vp, g_Vp);
    cudaGetSymbolAddress((void**)&Qb, g_Qb);
    cudaGetSymbolAddress((void**)&Kc, g_Kc);
    cudaGetSymbolAddress((void**)&Vc, g_Vc);
    cudaGetSymbolAddress((void**)&Sc, g_Sc);
    cudaGetSymbolAddress((void**)&AO, g_AO);

    // 1) QKV projections
    sgemm_nn<<<dim3(E_ / 128, M_ / 128), 256>>>(x, wq, Qp, M_, HQ_ * D_, E_);
    sgemm_nn<<<dim3((HKV_ * D_) / 128, M_ / 128), 256>>>(x, wk, Kp, M_, HKV_ * D_, E_);
    sgemm_nn<<<dim3((HKV_ * D_) / 128, M_ / 128), 256>>>(x, wv, Vp, M_, HKV_ * D_, E_);

    // 2) RoPE + layout transform (+ cache scatter via input_pos)
    rope_q_kernel<<<(B_ * S_ * HQ_ * 64) / 256, 256>>>(Qp, fc, Qb);
    rope_k_kernel<<<(B_ * S_ * HKV_ * 64) / 256, 256>>>(Kp, fc, ip, Kc);
    copy_v_kernel<<<(B_ * S_ * HKV_ * 32) / 256, 256>>>(Vp, ip, Vc);

    // 3) Attention: QK^T (scaled+masked) -> softmax -> P@V
    qkt_kernel<<<dim3(S_ / 128, S_ / 128, B_ * HQ_), 256>>>(Qb, Kc, Sc);
    softmax_rows<<<B_ * HQ_ * S_, 256>>>(Sc);
    pv_kernel<<<dim3(1, S_ / 128, B_ * HQ_), 256>>>(Sc, Vc, AO);

    // 4) Output projection -> d_out
    sgemm_nn<<<dim3(E_ / 128, M_ / 128), 256>>>(AO, wo, out, M_, E_, E_);
}

// round 3
// speedup vs baseline: 4.9023x; 4.9023x over previous
#include <cuda_runtime.h>
#include <cuda_bf16.h>
#include <float.h>
#include <math.h>
#include <stdint.h>

// Problem constants
#define B_   2
#define S_   2048
#define E_   4096
#define HQ_  32
#define HKV_ 8
#define D_   128
#define M_   (B_ * S_)          // 4096
#define SCALE_ 0.015625f        // 1/sqrt(4096)

// ---------------------------------------------------------------------------
// Scratch
// ---------------------------------------------------------------------------
__device__ float g_Qp[(size_t)M_ * (HQ_ * D_)];
__device__ float g_Kp[(size_t)M_ * (HKV_ * D_)];
__device__ float g_Vp[(size_t)M_ * (HKV_ * D_)];
__device__ float g_Qb[(size_t)B_ * HQ_ * S_ * D_];
__device__ float g_Kc[(size_t)B_ * HKV_ * S_ * D_];
__device__ float g_Vc[(size_t)B_ * HKV_ * S_ * D_];
__device__ float g_Sc[(size_t)B_ * HQ_ * S_ * S_];
__device__ float g_AO[(size_t)M_ * (HQ_ * D_)];

// ---------------------------------------------------------------------------
// tf32 mma helpers
// ---------------------------------------------------------------------------
__device__ __forceinline__ uint32_t f2tf32(float f) {
    uint32_t r;
    asm volatile("cvt.rna.tf32.f32 %0, %1;" : "=r"(r) : "f"(f));
    return r;
}
__device__ __forceinline__ void mma_tf32(float* c, const uint32_t* a, const uint32_t* b) {
    asm volatile(
        "mma.sync.aligned.m16n8k8.row.col.f32.tf32.tf32.f32 "
        "{%0,%1,%2,%3},{%4,%5,%6,%7},{%8,%9},{%0,%1,%2,%3};"
        : "+f"(c[0]), "+f"(c[1]), "+f"(c[2]), "+f"(c[3])
        : "r"(a[0]), "r"(a[1]), "r"(a[2]), "r"(a[3]), "r"(b[0]), "r"(b[1]));
}
__device__ __forceinline__ void cp16(void* smem, const void* gmem) {
    uint32_t s = (uint32_t)__cvta_generic_to_shared(smem);
    asm volatile("cp.async.cg.shared.global [%0], [%1], 16;\n" :: "r"(s), "l"(gmem));
}
#define CP_COMMIT() asm volatile("cp.async.commit_group;\n" ::: "memory")
#define CP_WAIT(n)  asm volatile("cp.async.wait_group %0;\n" :: "n"(n) : "memory")

#define KC 16
#define AS_STRIDE 20
#define BS_STRIDE 136

// ---------------------------------------------------------------------------
// tf32 GEMM NN: C[M,N] = A[M,K] @ B[K,N] row-major. 128x128 block, 256 thr.
// M,N mult of 128; K mult of 16.
// ---------------------------------------------------------------------------
__global__ __launch_bounds__(256, 2) void gemm_tf32_nn(
    const float* __restrict__ A, const float* __restrict__ Bm, float* __restrict__ C,
    int M, int N, int K)
{
    __shared__ float As[2][128][AS_STRIDE];
    __shared__ float Bs[2][KC][BS_STRIDE];
    const int tid = threadIdx.x;
    const int lane = tid & 31, warp = tid >> 5;
    const int wm = warp & 1, wn = warp >> 1;        // 2 x 4 warps
    const int m0 = blockIdx.y * 128, n0 = blockIdx.x * 128;

    float acc[4][4][4] = {};

    const int a_r = tid >> 2, a_c = (tid & 3) * 4;   // A: 128 x 16, two rows/thread
    const int b_k0 = tid >> 5, b_c = (tid & 31) * 4; // B: 16 x 128, two k-rows/thread

    const float* Aptr0 = A + (size_t)(m0 + a_r) * K + a_c;
    const float* Aptr1 = A + (size_t)(m0 + a_r + 64) * K + a_c;

    // prologue: stage 0
    {
        cp16(&As[0][a_r][a_c],      Aptr0);
        cp16(&As[0][a_r + 64][a_c], Aptr1);
        cp16(&Bs[0][b_k0][b_c],     Bm + (size_t)b_k0 * N + n0 + b_c);
        cp16(&Bs[0][b_k0 + 8][b_c], Bm + (size_t)(b_k0 + 8) * N + n0 + b_c);
        CP_COMMIT();
    }

    const int nchunk = K / KC;
    for (int ci = 0; ci < nchunk; ci++) {
        const int s = ci & 1;
        if (ci + 1 < nchunk) {
            const int kn = (ci + 1) * KC;
            cp16(&As[s ^ 1][a_r][a_c],      Aptr0 + kn);
            cp16(&As[s ^ 1][a_r + 64][a_c], Aptr1 + kn);
            cp16(&Bs[s ^ 1][b_k0][b_c],     Bm + (size_t)(kn + b_k0) * N + n0 + b_c);
            cp16(&Bs[s ^ 1][b_k0 + 8][b_c], Bm + (size_t)(kn + b_k0 + 8) * N + n0 + b_c);
            CP_COMMIT();
            CP_WAIT(1);
        } else {
            CP_WAIT(0);
        }
        __syncthreads();

        #pragma unroll
        for (int ks = 0; ks < 2; ks++) {
            const int k0 = ks * 8;
            uint32_t af[4][4], bf[4][2];
            #pragma unroll
            for (int mt = 0; mt < 4; mt++) {
                int r = wm * 64 + mt * 16 + (lane >> 2);
                int kc = k0 + (lane & 3);
                af[mt][0] = f2tf32(As[s][r][kc]);
                af[mt][1] = f2tf32(As[s][r + 8][kc]);
                af[mt][2] = f2tf32(As[s][r][kc + 4]);
                af[mt][3] = f2tf32(As[s][r + 8][kc + 4]);
            }
            #pragma unroll
            for (int nt = 0; nt < 4; nt++) {
                int cn = wn * 32 + nt * 8 + (lane >> 2);
                int kc = k0 + (lane & 3);
                bf[nt][0] = f2tf32(Bs[s][kc][cn]);
                bf[nt][1] = f2tf32(Bs[s][kc + 4][cn]);
            }
            #pragma unroll
            for (int mt = 0; mt < 4; mt++)
                #pragma unroll
                for (int nt = 0; nt < 4; nt++)
                    mma_tf32(acc[mt][nt], af[mt], bf[nt]);
        }
        __syncthreads();
    }

    #pragma unroll
    for (int mt = 0; mt < 4; mt++) {
        int r = m0 + wm * 64 + mt * 16 + (lane >> 2);
        #pragma unroll
        for (int nt = 0; nt < 4; nt++) {
            int cc = n0 + wn * 32 + nt * 8 + (lane & 3) * 2;
            *(float2*)(C + (size_t)r * N + cc)       = make_float2(acc[mt][nt][0], acc[mt][nt][1]);
            *(float2*)(C + (size_t)(r + 8) * N + cc) = make_float2(acc[mt][nt][2], acc[mt][nt][3]);
        }
    }
}

// ---------------------------------------------------------------------------
// tf32 QK^T: scores = scale * Q K^T with causal mask. Masked tiles skipped.
// ---------------------------------------------------------------------------
__global__ __launch_bounds__(256, 2) void qkt_tf32(
    const float* __restrict__ Qb, const float* __restrict__ Kc, float* __restrict__ Sc)
{
    const int m0 = blockIdx.y * 128, n0 = blockIdx.x * 128;
    if (n0 > m0) return;                 // fully masked tile: never read downstream
    const int bh = blockIdx.z;
    const int b = bh / HQ_, h = bh % HQ_;
    const int kvh = h / (HQ_ / HKV_);

    __shared__ float As[2][128][AS_STRIDE];   // Q rows
    __shared__ float Ks[2][128][AS_STRIDE];   // K rows (acts as col-major B)
    const int tid = threadIdx.x;
    const int lane = tid & 31, warp = tid >> 5;
    const int wm = warp & 1, wn = warp >> 1;

    const float* Qbase = Qb + (size_t)(b * HQ_ + h) * S_ * D_;
    const float* Kbase = Kc + (size_t)(b * HKV_ + kvh) * S_ * D_;

    float acc[4][4][4] = {};
    const int a_r = tid >> 2, a_c = (tid & 3) * 4;

    const float* Aptr0 = Qbase + (size_t)(m0 + a_r) * D_ + a_c;
    const float* Aptr1 = Qbase + (size_t)(m0 + a_r + 64) * D_ + a_c;
    const float* Bptr0 = Kbase + (size_t)(n0 + a_r) * D_ + a_c;
    const float* Bptr1 = Kbase + (size_t)(n0 + a_r + 64) * D_ + a_c;

    cp16(&As[0][a_r][a_c],      Aptr0);
    cp16(&As[0][a_r + 64][a_c], Aptr1);
    cp16(&Ks[0][a_r][a_c],      Bptr0);
    cp16(&Ks[0][a_r + 64][a_c], Bptr1);
    CP_COMMIT();

    const int nchunk = D_ / KC;   // 8
    for (int ci = 0; ci < nchunk; ci++) {
        const int s = ci & 1;
        if (ci + 1 < nchunk) {
            const int kn = (ci + 1) * KC;
            cp16(&As[s ^ 1][a_r][a_c],      Aptr0 + kn);
            cp16(&As[s ^ 1][a_r + 64][a_c], Aptr1 + kn);
            cp16(&Ks[s ^ 1][a_r][a_c],      Bptr0 + kn);
            cp16(&Ks[s ^ 1][a_r + 64][a_c], Bptr1 + kn);
            CP_COMMIT();
            CP_WAIT(1);
        } else {
            CP_WAIT(0);
        }
        __syncthreads();

        #pragma unroll
        for (int ks = 0; ks < 2; ks++) {
            const int k0 = ks * 8;
            uint32_t af[4][4], bf[4][2];
            #pragma unroll
            for (int mt = 0; mt < 4; mt++) {
                int r = wm * 64 + mt * 16 + (lane >> 2);
                int kc = k0 + (lane & 3);
                af[mt][0] = f2tf32(As[s][r][kc]);
                af[mt][1] = f2tf32(As[s][r + 8][kc]);
                af[mt][2] = f2tf32(As[s][r][kc + 4]);
                af[mt][3] = f2tf32(As[s][r + 8][kc + 4]);
            }
            #pragma unroll
            for (int nt = 0; nt < 4; nt++) {
                int cn = wn * 32 + nt * 8 + (lane >> 2);
                int kc = k0 + (lane & 3);
                bf[nt][0] = f2tf32(Ks[s][cn][kc]);
                bf[nt][1] = f2tf32(Ks[s][cn][kc + 4]);
            }
            #pragma unroll
            for (int mt = 0; mt < 4; mt++)
                #pragma unroll
                for (int nt = 0; nt < 4; nt++)
                    mma_tf32(acc[mt][nt], af[mt], bf[nt]);
        }
        __syncthreads();
    }

    float* Cbase = Sc + (size_t)bh * S_ * S_;
    #pragma unroll
    for (int mt = 0; mt < 4; mt++) {
        int r = m0 + wm * 64 + mt * 16 + (lane >> 2);
        #pragma unroll
        for (int nt = 0; nt < 4; nt++) {
            int cc = n0 + wn * 32 + nt * 8 + (lane & 3) * 2;
            float v0 = (cc     <= r) ? acc[mt][nt][0] * SCALE_ : -FLT_MAX;
            float v1 = (cc + 1 <= r) ? acc[mt][nt][1] * SCALE_ : -FLT_MAX;
            int r2 = r + 8;
            float v2 = (cc     <= r2) ? acc[mt][nt][2] * SCALE_ : -FLT_MAX;
            float v3 = (cc + 1 <= r2) ? acc[mt][nt][3] * SCALE_ : -FLT_MAX;
            *(float2*)(Cbase + (size_t)r  * S_ + cc) = make_float2(v0, v1);
            *(float2*)(Cbase + (size_t)r2 * S_ + cc) = make_float2(v2, v3);
        }
    }
}

// ---------------------------------------------------------------------------
// tf32 P@V with causal K-truncation
// ---------------------------------------------------------------------------
__global__ __launch_bounds__(256, 2) void pv_tf32(
    const float* __restrict__ Sc, const float* __restrict__ Vc, float* __restrict__ AO)
{
    const int bh = blockIdx.z;
    const int b = bh / HQ_, h = bh % HQ_;
    const int kvh = h / (HQ_ / HKV_);
    const int m0 = blockIdx.y * 128;

    __shared__ float As[2][128][AS_STRIDE];
    __shared__ float Bs[2][KC][BS_STRIDE];
    const int tid = threadIdx.x;
    const int lane = tid & 31, warp = tid >> 5;
    const int wm = warp & 1, wn = warp >> 1;

    const float* Pbase = Sc + (size_t)bh * S_ * S_;
    const float* Vbase = Vc + (size_t)(b * HKV_ + kvh) * S_ * D_;

    float acc[4][4][4] = {};
    const int a_r = tid >> 2, a_c = (tid & 3) * 4;
    const int b_k0 = tid >> 5, b_c = (tid & 31) * 4;

    const float* Aptr0 = Pbase + (size_t)(m0 + a_r) * S_ + a_c;
    const float* Aptr1 = Pbase + (size_t)(m0 + a_r + 64) * S_ + a_c;

    cp16(&As[0][a_r][a_c],      Aptr0);
    cp16(&As[0][a_r + 64][a_c], Aptr1);
    cp16(&Bs[0][b_k0][b_c],     Vbase + (size_t)b_k0 * D_ + b_c);
    cp16(&Bs[0][b_k0 + 8][b_c], Vbase + (size_t)(b_k0 + 8) * D_ + b_c);
    CP_COMMIT();

    const int nchunk = (m0 + 128) / KC;   // causal
    for (int ci = 0; ci < nchunk; ci++) {
        const int s = ci & 1;
        if (ci + 1 < nchunk) {
            const int kn = (ci + 1) * KC;
            cp16(&As[s ^ 1][a_r][a_c],      Aptr0 + kn);
            cp16(&As[s ^ 1][a_r + 64][a_c], Aptr1 + kn);
            cp16(&Bs[s ^ 1][b_k0][b_c],     Vbase + (size_t)(kn + b_k0) * D_ + b_c);
            cp16(&Bs[s ^ 1][b_k0 + 8][b_c], Vbase + (size_t)(kn + b_k0 + 8) * D_ + b_c);
            CP_COMMIT();
            CP_WAIT(1);
        } else {
            CP_WAIT(0);
        }
        __syncthreads();

        #pragma unroll
        for (int ks = 0; ks < 2; ks++) {
            const int k0 = ks * 8;
            uint32_t af[4][4], bf[4][2];
            #pragma unroll
            for (int mt = 0; mt < 4; mt++) {
                int r = wm * 64 + mt * 16 + (lane >> 2);
                int kc = k0 + (lane & 3);
                af[mt][0] = f2tf32(As[s][r][kc]);
                af[mt][1] = f2tf32(As[s][r + 8][kc]);
                af[mt][2] = f2tf32(As[s][r][kc + 4]);
                af[mt][3] = f2tf32(As[s][r + 8][kc + 4]);
            }
            #pragma unroll
            for (int nt = 0; nt < 4; nt++) {
                int cn = wn * 32 + nt * 8 + (lane >> 2);
                int kc = k0 + (lane & 3);
                bf[nt][0] = f2tf32(Bs[s][kc][cn]);
                bf[nt][1] = f2tf32(Bs[s][kc + 4][cn]);
            }
            #pragma unroll
            for (int mt = 0; mt < 4; mt++)
                #pragma unroll
                for (int nt = 0; nt < 4; nt++)
                    mma_tf32(acc[mt][nt], af[mt], bf[nt]);
        }
        __syncthreads();
    }

    #pragma unroll
    for (int mt = 0; mt < 4; mt++) {
        int r = m0 + wm * 64 + mt * 16 + (lane >> 2);
        #pragma unroll
        for (int nt = 0; nt < 4; nt++) {
            int cc = h * D_ + wn * 32 + nt * 8 + (lane & 3) * 2;
            float* C0 = AO + (size_t)(b * S_ + r) * (HQ_ * D_) + cc;
            float* C1 = AO + (size_t)(b * S_ + r + 8) * (HQ_ * D_) + cc;
            *(float2*)C0 = make_float2(acc[mt][nt][0], acc[mt][nt][1]);
            *(float2*)C1 = make_float2(acc[mt][nt][2], acc[mt][nt][3]);
        }
    }
}

// ---------------------------------------------------------------------------
// RoPE / cache scatter
// ---------------------------------------------------------------------------
__global__ void rope_q_kernel(const float* __restrict__ Qp, const float* __restrict__ fc,
                              float* __restrict__ Qb) {
    int i = blockIdx.x * 256 + threadIdx.x;
    int p = i & 63;
    int h = (i >> 6) & (HQ_ - 1);
    int s = (i >> 11) & (S_ - 1);
    int b = i >> 22;
    float2 qv = ((const float2*)Qp)[((size_t)(b * S_ + s) * (HQ_ * D_) + h * D_) / 2 + p];
    float2 cs = ((const float2*)fc)[(size_t)s * 64 + p];
    float2 o;
    o.x = qv.x * cs.x - qv.y * cs.y;
    o.y = qv.x * cs.y + qv.y * cs.x;
    ((float2*)Qb)[((size_t)((b * HQ_ + h) * S_ + s) * D_) / 2 + p] = o;
}

__global__ void rope_k_kernel(const float* __restrict__ Kp, const float* __restrict__ fc,
                              const int* __restrict__ input_pos, float* __restrict__ Kc) {
    int i = blockIdx.x * 256 + threadIdx.x;
    int p = i & 63;
    int h = (i >> 6) & (HKV_ - 1);
    int s = (i >> 9) & (S_ - 1);
    int b = i >> 20;
    int pos = input_pos[s];
    float2 kv = ((const float2*)Kp)[((size_t)(b * S_ + s) * (HKV_ * D_) + h * D_) / 2 + p];
    float2 cs = ((const float2*)fc)[(size_t)s * 64 + p];
    float2 o;
    o.x = kv.x * cs.x - kv.y * cs.y;
    o.y = kv.x * cs.y + kv.y * cs.x;
    ((float2*)Kc)[((size_t)((b * HKV_ + h) * S_ + pos) * D_) / 2 + p] = o;
}

__global__ void copy_v_kernel(const float* __restrict__ Vp, const int* __restrict__ input_pos,
                              float* __restrict__ Vc) {
    int i = blockIdx.x * 256 + threadIdx.x;
    int c = i & 31;
    int h = (i >> 5) & (HKV_ - 1);
    int s = (i >> 8) & (S_ - 1);
    int b = i >> 19;
    int pos = input_pos[s];
    float4 v = ((const float4*)Vp)[((size_t)(b * S_ + s) * (HKV_ * D_) + h * D_) / 4 + c];
    ((float4*)Vc)[((size_t)((b * HKV_ + h) * S_ + pos) * D_) / 4 + c] = v;
}

// ---------------------------------------------------------------------------
// Row softmax, causal-truncated length L = (q/128 + 1)*128
// ---------------------------------------------------------------------------
__device__ __forceinline__ float warpMax(float v) {
    #pragma unroll
    for (int o = 16; o; o >>= 1) v = fmaxf(v, __shfl_xor_sync(0xffffffffu, v, o));
    return v;
}
__device__ __forceinline__ float warpSum(float v) {
    #pragma unroll
    for (int o = 16; o; o >>= 1) v += __shfl_xor_sync(0xffffffffu, v, o);
    return v;
}

__global__ void softmax_rows(float* __restrict__ Sc) {
    const long long row = blockIdx.x;
    const int q = (int)(row & (S_ - 1));
    const int L = ((q >> 7) + 1) << 7;
    float* p = Sc + row * (long long)S_;
    const int tid = threadIdx.x;
    __shared__ float sm[8], ss[8];

    float v[8];
    const int n = (L + 255) >> 8;
    float m = -FLT_MAX;
    for (int i = 0; i < n; i++) {
        int j = tid + i * 256;
        v[i] = (j < L) ? p[j] : -FLT_MAX;
        m = fmaxf(m, v[i]);
    }
    m = warpMax(m);
    if ((tid & 31) == 0) sm[tid >> 5] = m;
    __syncthreads();
    float bm = -FLT_MAX;
    #pragma unroll
    for (int i = 0; i < 8; i++) bm = fmaxf(bm, sm[i]);

    float sum = 0.f;
    for (int i = 0; i < n; i++) { v[i] = __expf(v[i] - bm); sum += v[i]; }
    sum = warpSum(sum);
    if ((tid & 31) == 0) ss[tid >> 5] = sum;
    __syncthreads();
    float bs = 0.f;
    #pragma unroll
    for (int i = 0; i < 8; i++) bs += ss[i];
    float inv = 1.0f / bs;
    for (int i = 0; i < n; i++) {
        int j = tid + i * 256;
        if (j < L) p[j] = v[i] * inv;
    }
}

// ---------------------------------------------------------------------------
// kernel_launch
// ---------------------------------------------------------------------------
extern "C" void kernel_launch(void* const* d_in, const int* in_sizes, int n_in,
                              void* d_out, int out_size) {
    const float* x  = (const float*)d_in[0];
    const int*   ip = (const int*)  d_in[1];
    const float* fc = (const float*)d_in[2];
    const float* wq = (const float*)d_in[3];
    const float* wk = (const float*)d_in[4];
    const float* wv = (const float*)d_in[5];
    const float* wo = (const float*)d_in[6];
    float* out = (float*)d_out;

    float *Qp, *Kp, *Vp, *Qb, *Kc, *Vc, *Sc, *AO;
    cudaGetSymbolAddress((void**)&Qp, g_Qp);
    cudaGetSymbolAddress((void**)&Kp, g_Kp);
    cudaGetSymbolAddress((void**)&Vp, g_Vp);
    cudaGetSymbolAddress((void**)&Qb, g_Qb);
    cudaGetSymbolAddress((void**)&Kc, g_Kc);
    cudaGetSymbolAddress((void**)&Vc, g_Vc);
    cudaGetSymbolAddress((void**)&Sc, g_Sc);
    cudaGetSymbolAddress((void**)&AO, g_AO);

    // 1) QKV projections (tf32 tensor cores)
    gemm_tf32_nn<<<dim3(E_ / 128, M_ / 128), 256>>>(x, wq, Qp, M_, HQ_ * D_, E_);
    gemm_tf32_nn<<<dim3((HKV_ * D_) / 128, M_ / 128), 256>>>(x, wk, Kp, M_, HKV_ * D_, E_);
    gemm_tf32_nn<<<dim3((HKV_ * D_) / 128, M_ / 128), 256>>>(x, wv, Vp, M_, HKV_ * D_, E_);

    // 2) RoPE + cache scatter
    rope_q_kernel<<<(B_ * S_ * HQ_ * 64) / 256, 256>>>(Qp, fc, Qb);
    rope_k_kernel<<<(B_ * S_ * HKV_ * 64) / 256, 256>>>(Kp, fc, ip, Kc);
    copy_v_kernel<<<(B_ * S_ * HKV_ * 32) / 256, 256>>>(Vp, ip, Vc);

    // 3) Attention
    qkt_tf32<<<dim3(S_ / 128, S_ / 128, B_ * HQ_), 256>>>(Qb, Kc, Sc);
    softmax_rows<<<B_ * HQ_ * S_, 256>>>(Sc);
    pv_tf32<<<dim3(1, S_ / 128, B_ * HQ_), 256>>>(Sc, Vc, AO);

    // 4) Output projection
    gemm_tf32_nn<<<dim3(E_ / 128, M_ / 128), 256>>>(AO, wo, out, M_, E_, E_);
}

// round 4
// speedup vs baseline: 5.3784x; 1.0971x over previous
#include <cuda_runtime.h>
#include <cuda_bf16.h>
#include <float.h>
#include <math.h>
#include <stdint.h>

// Problem constants
#define B_   2
#define S_   2048
#define E_   4096
#define HQ_  32
#define HKV_ 8
#define D_   128
#define M_   (B_ * S_)          // 4096
#define SCALE_ 0.015625f        // 1/sqrt(4096)

// ---------------------------------------------------------------------------
// Scratch
// ---------------------------------------------------------------------------
__device__ float g_Qp[(size_t)M_ * (HQ_ * D_)];
__device__ float g_Kp[(size_t)M_ * (HKV_ * D_)];
__device__ float g_Vp[(size_t)M_ * (HKV_ * D_)];
__device__ float g_Qb[(size_t)B_ * HQ_ * S_ * D_];
__device__ float g_Kc[(size_t)B_ * HKV_ * S_ * D_];
__device__ float g_Vc[(size_t)B_ * HKV_ * S_ * D_];
__device__ float g_AO[(size_t)M_ * (HQ_ * D_)];

// ---------------------------------------------------------------------------
// tf32 mma helpers
// ---------------------------------------------------------------------------
__device__ __forceinline__ uint32_t f2tf32(float f) {
    uint32_t r;
    asm volatile("cvt.rna.tf32.f32 %0, %1;" : "=r"(r) : "f"(f));
    return r;
}
__device__ __forceinline__ void mma_tf32(float* c, const uint32_t* a, const uint32_t* b) {
    asm volatile(
        "mma.sync.aligned.m16n8k8.row.col.f32.tf32.tf32.f32 "
        "{%0,%1,%2,%3},{%4,%5,%6,%7},{%8,%9},{%0,%1,%2,%3};"
        : "+f"(c[0]), "+f"(c[1]), "+f"(c[2]), "+f"(c[3])
        : "r"(a[0]), "r"(a[1]), "r"(a[2]), "r"(a[3]), "r"(b[0]), "r"(b[1]));
}
__device__ __forceinline__ void cp16(void* smem, const void* gmem) {
    uint32_t s = (uint32_t)__cvta_generic_to_shared(smem);
    asm volatile("cp.async.cg.shared.global [%0], [%1], 16;\n" :: "r"(s), "l"(gmem));
}
#define CP_COMMIT() asm volatile("cp.async.commit_group;\n" ::: "memory")
#define CP_WAIT(n)  asm volatile("cp.async.wait_group %0;\n" :: "n"(n) : "memory")

#define KC 16
#define AS_STRIDE 20
#define BS_STRIDE 136

// ---------------------------------------------------------------------------
// tf32 GEMM NN (unchanged from R3)
// ---------------------------------------------------------------------------
__global__ __launch_bounds__(256, 2) void gemm_tf32_nn(
    const float* __restrict__ A, const float* __restrict__ Bm, float* __restrict__ C,
    int M, int N, int K)
{
    __shared__ float As[2][128][AS_STRIDE];
    __shared__ float Bs[2][KC][BS_STRIDE];
    const int tid = threadIdx.x;
    const int lane = tid & 31, warp = tid >> 5;
    const int wm = warp & 1, wn = warp >> 1;
    const int m0 = blockIdx.y * 128, n0 = blockIdx.x * 128;

    float acc[4][4][4] = {};

    const int a_r = tid >> 2, a_c = (tid & 3) * 4;
    const int b_k0 = tid >> 5, b_c = (tid & 31) * 4;

    const float* Aptr0 = A + (size_t)(m0 + a_r) * K + a_c;
    const float* Aptr1 = A + (size_t)(m0 + a_r + 64) * K + a_c;

    {
        cp16(&As[0][a_r][a_c],      Aptr0);
        cp16(&As[0][a_r + 64][a_c], Aptr1);
        cp16(&Bs[0][b_k0][b_c],     Bm + (size_t)b_k0 * N + n0 + b_c);
        cp16(&Bs[0][b_k0 + 8][b_c], Bm + (size_t)(b_k0 + 8) * N + n0 + b_c);
        CP_COMMIT();
    }

    const int nchunk = K / KC;
    for (int ci = 0; ci < nchunk; ci++) {
        const int s = ci & 1;
        if (ci + 1 < nchunk) {
            const int kn = (ci + 1) * KC;
            cp16(&As[s ^ 1][a_r][a_c],      Aptr0 + kn);
            cp16(&As[s ^ 1][a_r + 64][a_c], Aptr1 + kn);
            cp16(&Bs[s ^ 1][b_k0][b_c],     Bm + (size_t)(kn + b_k0) * N + n0 + b_c);
            cp16(&Bs[s ^ 1][b_k0 + 8][b_c], Bm + (size_t)(kn + b_k0 + 8) * N + n0 + b_c);
            CP_COMMIT();
            CP_WAIT(1);
        } else {
            CP_WAIT(0);
        }
        __syncthreads();

        #pragma unroll
        for (int ks = 0; ks < 2; ks++) {
            const int k0 = ks * 8;
            uint32_t af[4][4], bf[4][2];
            #pragma unroll
            for (int mt = 0; mt < 4; mt++) {
                int r = wm * 64 + mt * 16 + (lane >> 2);
                int kc = k0 + (lane & 3);
                af[mt][0] = f2tf32(As[s][r][kc]);
                af[mt][1] = f2tf32(As[s][r + 8][kc]);
                af[mt][2] = f2tf32(As[s][r][kc + 4]);
                af[mt][3] = f2tf32(As[s][r + 8][kc + 4]);
            }
            #pragma unroll
            for (int nt = 0; nt < 4; nt++) {
                int cn = wn * 32 + nt * 8 + (lane >> 2);
                int kc = k0 + (lane & 3);
                bf[nt][0] = f2tf32(Bs[s][kc][cn]);
                bf[nt][1] = f2tf32(Bs[s][kc + 4][cn]);
            }
            #pragma unroll
            for (int mt = 0; mt < 4; mt++)
                #pragma unroll
                for (int nt = 0; nt < 4; nt++)
                    mma_tf32(acc[mt][nt], af[mt], bf[nt]);
        }
        __syncthreads();
    }

    #pragma unroll
    for (int mt = 0; mt < 4; mt++) {
        int r = m0 + wm * 64 + mt * 16 + (lane >> 2);
        #pragma unroll
        for (int nt = 0; nt < 4; nt++) {
            int cc = n0 + wn * 32 + nt * 8 + (lane & 3) * 2;
            *(float2*)(C + (size_t)r * N + cc)       = make_float2(acc[mt][nt][0], acc[mt][nt][1]);
            *(float2*)(C + (size_t)(r + 8) * N + cc) = make_float2(acc[mt][nt][2], acc[mt][nt][3]);
        }
    }
}

// ---------------------------------------------------------------------------
// Fused flash attention (tf32). One block = one (b,h) x 128-row Q tile.
// 8 warps, warp w owns rows [16w, 16w+16). K/V streamed in 64-row tiles,
// cp.async double buffered. Online softmax; no scores scratch.
// ---------------------------------------------------------------------------
#define FSTR 132   // padded row stride (floats) for 128-col tiles

__device__ __forceinline__ void fa_load_kv(
    float* Ks, float* Vs, int stage,
    const float* __restrict__ Kp, const float* __restrict__ Vp, int tid)
{
    float* kd = Ks + stage * 64 * FSTR;
    float* vd = Vs + stage * 64 * FSTR;
    #pragma unroll
    for (int i = 0; i < 8; i++) {
        int e = i * 256 + tid;          // 0..2047 float4s
        int r = e >> 5, c4 = (e & 31) * 4;
        cp16(kd + r * FSTR + c4, Kp + (size_t)r * D_ + c4);
        cp16(vd + r * FSTR + c4, Vp + (size_t)r * D_ + c4);
    }
}

__global__ __launch_bounds__(256, 1) void flash_tf32(
    const float* __restrict__ Qb, const float* __restrict__ Kc,
    const float* __restrict__ Vc, float* __restrict__ AO)
{
    extern __shared__ float smbuf[];
    float* Qs = smbuf;                        // [128][FSTR]
    float* Ks = smbuf + 128 * FSTR;           // [2][64][FSTR]
    float* Vs = smbuf + 128 * FSTR + 2 * 64 * FSTR;

    const int qt = (S_ / 128 - 1) - blockIdx.x;   // heavy tiles first
    const int bh = blockIdx.y;
    const int b = bh / HQ_, h = bh % HQ_;
    const int kvh = h / (HQ_ / HKV_);
    const int m0 = qt * 128;

    const int tid = threadIdx.x, lane = tid & 31, warp = tid >> 5;
    const int g = lane >> 2, t = lane & 3;

    const float* Qbase = Qb + (size_t)(b * HQ_ + h) * S_ * D_ + (size_t)m0 * D_;
    const float* Kbase = Kc + (size_t)(b * HKV_ + kvh) * S_ * D_;
    const float* Vbase = Vc + (size_t)(b * HKV_ + kvh) * S_ * D_;

    // stage Q tile (group 0)
    #pragma unroll
    for (int i = 0; i < 16; i++) {
        int e = i * 256 + tid;
        int r = e >> 5, c4 = (e & 31) * 4;
        cp16(Qs + r * FSTR + c4, Qbase + (size_t)r * D_ + c4);
    }
    CP_COMMIT();

    const int nkt = 2 * qt + 2;
    fa_load_kv(Ks, Vs, 0, Kbase, Vbase, tid);
    CP_COMMIT();

    uint32_t qf[16][4];            // Q fragments, loaded once at kt==0
    float Oacc[16][4] = {};        // D=128 -> 16 n-frags
    float mrow0 = -FLT_MAX, mrow1 = -FLT_MAX;
    float lrow0 = 0.f, lrow1 = 0.f;

    const int srcA = (lane & ~3) | (t >> 1);
    const int srcB = srcA + 2;
    const bool odd = (t & 1);

    for (int kt = 0; kt < nkt; kt++) {
        const int s = kt & 1;
        if (kt + 1 < nkt) {
            fa_load_kv(Ks, Vs, s ^ 1, Kbase + (size_t)(kt + 1) * 64 * D_,
                       Vbase + (size_t)(kt + 1) * 64 * D_, tid);
            CP_COMMIT();
            CP_WAIT(1);
        } else {
            CP_WAIT(0);
        }
        __syncthreads();

        if (kt == 0) {
            // Q fragments from smem (once)
            #pragma unroll
            for (int ks = 0; ks < 16; ks++) {
                int r = warp * 16 + g, kc = ks * 8 + t;
                qf[ks][0] = f2tf32(Qs[r * FSTR + kc]);
                qf[ks][1] = f2tf32(Qs[(r + 8) * FSTR + kc]);
                qf[ks][2] = f2tf32(Qs[r * FSTR + kc + 4]);
                qf[ks][3] = f2tf32(Qs[(r + 8) * FSTR + kc + 4]);
            }
        }

        const float* ks_base = Ks + s * 64 * FSTR;
        const float* vs_base = Vs + s * 64 * FSTR;

        // ---- S = Q K^T (128x64 per block; 16x64 per warp) ----
        float sc[8][4];
        #pragma unroll
        for (int nf = 0; nf < 8; nf++) {
            sc[nf][0] = sc[nf][1] = sc[nf][2] = sc[nf][3] = 0.f;
        }
        #pragma unroll
        for (int ks = 0; ks < 16; ks++) {
            #pragma unroll
            for (int nf = 0; nf < 8; nf++) {
                uint32_t bb[2];
                const float* kp = ks_base + (nf * 8 + g) * FSTR + ks * 8 + t;
                bb[0] = f2tf32(kp[0]);
                bb[1] = f2tf32(kp[4]);
                mma_tf32(sc[nf], qf[ks], bb);
            }
        }

        // ---- scale + causal mask ----
        const int r0 = m0 + warp * 16 + g;
        const int r1 = r0 + 8;
        const bool diag = (kt >= 2 * qt);
        #pragma unroll
        for (int nf = 0; nf < 8; nf++) {
            int c0 = kt * 64 + nf * 8 + 2 * t;
            sc[nf][0] *= SCALE_; sc[nf][1] *= SCALE_;
            sc[nf][2] *= SCALE_; sc[nf][3] *= SCALE_;
            if (diag) {
                if (c0     > r0) sc[nf][0] = -FLT_MAX;
                if (c0 + 1 > r0) sc[nf][1] = -FLT_MAX;
                if (c0     > r1) sc[nf][2] = -FLT_MAX;
                if (c0 + 1 > r1) sc[nf][3] = -FLT_MAX;
            }
        }

        // ---- online softmax ----
        float mx0 = -FLT_MAX, mx1 = -FLT_MAX;
        #pragma unroll
        for (int nf = 0; nf < 8; nf++) {
            mx0 = fmaxf(mx0, fmaxf(sc[nf][0], sc[nf][1]));
            mx1 = fmaxf(mx1, fmaxf(sc[nf][2], sc[nf][3]));
        }
        mx0 = fmaxf(mx0, __shfl_xor_sync(0xffffffffu, mx0, 1));
        mx0 = fmaxf(mx0, __shfl_xor_sync(0xffffffffu, mx0, 2));
        mx1 = fmaxf(mx1, __shfl_xor_sync(0xffffffffu, mx1, 1));
        mx1 = fmaxf(mx1, __shfl_xor_sync(0xffffffffu, mx1, 2));

        float mnew0 = fmaxf(mrow0, mx0), mnew1 = fmaxf(mrow1, mx1);
        float f0 = __expf(mrow0 - mnew0), f1 = __expf(mrow1 - mnew1);
        mrow0 = mnew0; mrow1 = mnew1;

        float rs0 = 0.f, rs1 = 0.f;
        #pragma unroll
        for (int nf = 0; nf < 8; nf++) {
            sc[nf][0] = __expf(sc[nf][0] - mnew0);
            sc[nf][1] = __expf(sc[nf][1] - mnew0);
            sc[nf][2] = __expf(sc[nf][2] - mnew1);
            sc[nf][3] = __expf(sc[nf][3] - mnew1);
            rs0 += sc[nf][0] + sc[nf][1];
            rs1 += sc[nf][2] + sc[nf][3];
        }
        rs0 += __shfl_xor_sync(0xffffffffu, rs0, 1);
        rs0 += __shfl_xor_sync(0xffffffffu, rs0, 2);
        rs1 += __shfl_xor_sync(0xffffffffu, rs1, 1);
        rs1 += __shfl_xor_sync(0xffffffffu, rs1, 2);
        lrow0 = lrow0 * f0 + rs0;
        lrow1 = lrow1 * f1 + rs1;

        #pragma unroll
        for (int nf2 = 0; nf2 < 16; nf2++) {
            Oacc[nf2][0] *= f0; Oacc[nf2][1] *= f0;
            Oacc[nf2][2] *= f1; Oacc[nf2][3] *= f1;
        }

        // ---- O += P V : relayout P via quad shuffles, then mma ----
        #pragma unroll
        for (int kc2 = 0; kc2 < 8; kc2++) {
            float vA0 = __shfl_sync(0xffffffffu, sc[kc2][0], srcA);
            float vA1 = __shfl_sync(0xffffffffu, sc[kc2][1], srcA);
            float vA2 = __shfl_sync(0xffffffffu, sc[kc2][2], srcA);
            float vA3 = __shfl_sync(0xffffffffu, sc[kc2][3], srcA);
            float vB0 = __shfl_sync(0xffffffffu, sc[kc2][0], srcB);
            float vB1 = __shfl_sync(0xffffffffu, sc[kc2][1], srcB);
            float vB2 = __shfl_sync(0xffffffffu, sc[kc2][2], srcB);
            float vB3 = __shfl_sync(0xffffffffu, sc[kc2][3], srcB);
            uint32_t aP[4];
            aP[0] = f2tf32(odd ? vA1 : vA0);
            aP[1] = f2tf32(odd ? vA3 : vA2);
            aP[2] = f2tf32(odd ? vB1 : vB0);
            aP[3] = f2tf32(odd ? vB3 : vB2);

            #pragma unroll
            for (int nf2 = 0; nf2 < 16; nf2++) {
                uint32_t bv[2];
                const float* vp = vs_base + (kc2 * 8 + t) * FSTR + nf2 * 8 + g;
                bv[0] = f2tf32(vp[0]);
                bv[1] = f2tf32(vp[4 * FSTR]);
                mma_tf32(Oacc[nf2], aP, bv);
            }
        }

        __syncthreads();   // all reads of stage s done before next iter overwrites
    }

    // ---- normalize + store ----
    const float inv0 = 1.0f / lrow0, inv1 = 1.0f / lrow1;
    const int r0 = m0 + warp * 16 + g;
    #pragma unroll
    for (int nf2 = 0; nf2 < 16; nf2++) {
        int cc = h * D_ + nf2 * 8 + 2 * t;
        float* C0 = AO + (size_t)(b * S_ + r0) * (HQ_ * D_) + cc;
        float* C1 = AO + (size_t)(b * S_ + r0 + 8) * (HQ_ * D_) + cc;
        *(float2*)C0 = make_float2(Oacc[nf2][0] * inv0, Oacc[nf2][1] * inv0);
        *(float2*)C1 = make_float2(Oacc[nf2][2] * inv1, Oacc[nf2][3] * inv1);
    }
}

#define FLASH_SMEM ((128 * FSTR + 2 * 64 * FSTR + 2 * 64 * FSTR) * 4)

// ---------------------------------------------------------------------------
// RoPE / cache scatter
// ---------------------------------------------------------------------------
__global__ void rope_q_kernel(const float* __restrict__ Qp, const float* __restrict__ fc,
                              float* __restrict__ Qb) {
    int i = blockIdx.x * 256 + threadIdx.x;
    int p = i & 63;
    int h = (i >> 6) & (HQ_ - 1);
    int s = (i >> 11) & (S_ - 1);
    int b = i >> 22;
    float2 qv = ((const float2*)Qp)[((size_t)(b * S_ + s) * (HQ_ * D_) + h * D_) / 2 + p];
    float2 cs = ((const float2*)fc)[(size_t)s * 64 + p];
    float2 o;
    o.x = qv.x * cs.x - qv.y * cs.y;
    o.y = qv.x * cs.y + qv.y * cs.x;
    ((float2*)Qb)[((size_t)((b * HQ_ + h) * S_ + s) * D_) / 2 + p] = o;
}

__global__ void rope_k_kernel(const float* __restrict__ Kp, const float* __restrict__ fc,
                              const int* __restrict__ input_pos, float* __restrict__ Kc) {
    int i = blockIdx.x * 256 + threadIdx.x;
    int p = i & 63;
    int h = (i >> 6) & (HKV_ - 1);
    int s = (i >> 9) & (S_ - 1);
    int b = i >> 20;
    int pos = input_pos[s];
    float2 kv = ((const float2*)Kp)[((size_t)(b * S_ + s) * (HKV_ * D_) + h * D_) / 2 + p];
    float2 cs = ((const float2*)fc)[(size_t)s * 64 + p];
    float2 o;
    o.x = kv.x * cs.x - kv.y * cs.y;
    o.y = kv.x * cs.y + kv.y * cs.x;
    ((float2*)Kc)[((size_t)((b * HKV_ + h) * S_ + pos) * D_) / 2 + p] = o;
}

__global__ void copy_v_kernel(const float* __restrict__ Vp, const int* __restrict__ input_pos,
                              float* __restrict__ Vc) {
    int i = blockIdx.x * 256 + threadIdx.x;
    int c = i & 31;
    int h = (i >> 5) & (HKV_ - 1);
    int s = (i >> 8) & (S_ - 1);
    int b = i >> 19;
    int pos = input_pos[s];
    float4 v = ((const float4*)Vp)[((size_t)(b * S_ + s) * (HKV_ * D_) + h * D_) / 4 + c];
    ((float4*)Vc)[((size_t)((b * HKV_ + h) * S_ + pos) * D_) / 4 + c] = v;
}

// ---------------------------------------------------------------------------
// kernel_launch
// ---------------------------------------------------------------------------
extern "C" void kernel_launch(void* const* d_in, const int* in_sizes, int n_in,
                              void* d_out, int out_size) {
    const float* x  = (const float*)d_in[0];
    const int*   ip = (const int*)  d_in[1];
    const float* fc = (const float*)d_in[2];
    const float* wq = (const float*)d_in[3];
    const float* wk = (const float*)d_in[4];
    const float* wv = (const float*)d_in[5];
    const float* wo = (const float*)d_in[6];
    float* out = (float*)d_out;

    float *Qp, *Kp, *Vp, *Qb, *Kc, *Vc, *AO;
    cudaGetSymbolAddress((void**)&Qp, g_Qp);
    cudaGetSymbolAddress((void**)&Kp, g_Kp);
    cudaGetSymbolAddress((void**)&Vp, g_Vp);
    cudaGetSymbolAddress((void**)&Qb, g_Qb);
    cudaGetSymbolAddress((void**)&Kc, g_Kc);
    cudaGetSymbolAddress((void**)&Vc, g_Vc);
    cudaGetSymbolAddress((void**)&AO, g_AO);

    static int smem_set = 0;
    if (!smem_set) {
        cudaFuncSetAttribute(flash_tf32, cudaFuncAttributeMaxDynamicSharedMemorySize, FLASH_SMEM);
        smem_set = 1;
    }

    // 1) QKV projections (tf32 tensor cores)
    gemm_tf32_nn<<<dim3(E_ / 128, M_ / 128), 256>>>(x, wq, Qp, M_, HQ_ * D_, E_);
    gemm_tf32_nn<<<dim3((HKV_ * D_) / 128, M_ / 128), 256>>>(x, wk, Kp, M_, HKV_ * D_, E_);
    gemm_tf32_nn<<<dim3((HKV_ * D_) / 128, M_ / 128), 256>>>(x, wv, Vp, M_, HKV_ * D_, E_);

    // 2) RoPE + cache scatter
    rope_q_kernel<<<(B_ * S_ * HQ_ * 64) / 256, 256>>>(Qp, fc, Qb);
    rope_k_kernel<<<(B_ * S_ * HKV_ * 64) / 256, 256>>>(Kp, fc, ip, Kc);
    copy_v_kernel<<<(B_ * S_ * HKV_ * 32) / 256, 256>>>(Vp, ip, Vc);

    // 3) Fused flash attention (no scores scratch)
    flash_tf32<<<dim3(S_ / 128, B_ * HQ_), 256, FLASH_SMEM>>>(Qb, Kc, Vc, AO);

    // 4) Output projection
    gemm_tf32_nn<<<dim3(E_ / 128, M_ / 128), 256>>>(AO, wo, out, M_, E_, E_);
}

// round 5
// speedup vs baseline: 5.4581x; 1.0148x over previous
#include <cuda_runtime.h>
#include <cuda_bf16.h>
#include <float.h>
#include <math.h>
#include <stdint.h>

// Problem constants
#define B_   2
#define S_   2048
#define E_   4096
#define HQ_  32
#define HKV_ 8
#define D_   128
#define M_   (B_ * S_)          // 4096
#define SCALE_ 0.015625f        // 1/sqrt(4096)

// ---------------------------------------------------------------------------
// Scratch: Qb/Kc/Vc hold tf32 BIT PATTERNS (uint32), AO holds fp32
// ---------------------------------------------------------------------------
__device__ uint32_t g_Qb[(size_t)B_ * HQ_ * S_ * D_];   // roped+scaled Q, tf32 bits
__device__ uint32_t g_Kc[(size_t)B_ * HKV_ * S_ * D_];  // roped K, tf32 bits
__device__ uint32_t g_Vc[(size_t)B_ * HKV_ * S_ * D_];  // V, tf32 bits
__device__ float    g_AO[(size_t)M_ * (HQ_ * D_)];      // attn out fp32

// ---------------------------------------------------------------------------
// tf32 mma helpers
// ---------------------------------------------------------------------------
__device__ __forceinline__ uint32_t f2tf32(float f) {
    uint32_t r;
    asm volatile("cvt.rna.tf32.f32 %0, %1;" : "=r"(r) : "f"(f));
    return r;
}
__device__ __forceinline__ void mma_tf32(float* c, const uint32_t* a, const uint32_t* b) {
    asm volatile(
        "mma.sync.aligned.m16n8k8.row.col.f32.tf32.tf32.f32 "
        "{%0,%1,%2,%3},{%4,%5,%6,%7},{%8,%9},{%0,%1,%2,%3};"
        : "+f"(c[0]), "+f"(c[1]), "+f"(c[2]), "+f"(c[3])
        : "r"(a[0]), "r"(a[1]), "r"(a[2]), "r"(a[3]), "r"(b[0]), "r"(b[1]));
}
__device__ __forceinline__ void cp16(void* smem, const void* gmem) {
    uint32_t s = (uint32_t)__cvta_generic_to_shared(smem);
    asm volatile("cp.async.cg.shared.global [%0], [%1], 16;\n" :: "r"(s), "l"(gmem));
}
#define CP_COMMIT() asm volatile("cp.async.commit_group;\n" ::: "memory")
#define CP_WAIT(n)  asm volatile("cp.async.wait_group %0;\n" :: "n"(n) : "memory")

#define KC 16
#define AS_STRIDE 20
#define BS_STRIDE 136

// ---------------------------------------------------------------------------
// tf32 GEMM with fused epilogues.
//   MODE 0: plain fp32 C = A @ B           (out-projection)
//   MODE 1: Q proj: RoPE + *SCALE_ + transpose -> Ok as tf32 bits
//   MODE 2: K+V proj fused: blockIdx.x<8 -> K (RoPE, scatter via ip) to Ok,
//           blockIdx.x>=8 -> V (copy, scatter via ip) to Ov. tf32 bits.
// ---------------------------------------------------------------------------
template<int MODE>
__global__ __launch_bounds__(256, 2) void gemm_ep(
    const float* __restrict__ A, const float* __restrict__ Bk, const float* __restrict__ Bv,
    float* __restrict__ C, uint32_t* __restrict__ Ok, uint32_t* __restrict__ Ov,
    const float* __restrict__ fc, const int* __restrict__ ip,
    int M, int N, int K)
{
    __shared__ float As[2][128][AS_STRIDE];
    __shared__ float Bs[2][KC][BS_STRIDE];
    const int tid = threadIdx.x;
    const int lane = tid & 31, warp = tid >> 5;
    const int wm = warp & 1, wn = warp >> 1;
    const int m0 = blockIdx.y * 128;

    const float* Bm;
    int n0;
    bool isV = false;
    if (MODE == 2) {
        if (blockIdx.x < 8) { Bm = Bk; n0 = blockIdx.x * 128; }
        else                { Bm = Bv; n0 = (blockIdx.x - 8) * 128; isV = true; }
    } else {
        Bm = Bk; n0 = blockIdx.x * 128;
    }

    float acc[4][4][4] = {};

    const int a_r = tid >> 2, a_c = (tid & 3) * 4;
    const int b_k0 = tid >> 5, b_c = (tid & 31) * 4;

    const float* Aptr0 = A + (size_t)(m0 + a_r) * K + a_c;
    const float* Aptr1 = A + (size_t)(m0 + a_r + 64) * K + a_c;

    {
        cp16(&As[0][a_r][a_c],      Aptr0);
        cp16(&As[0][a_r + 64][a_c], Aptr1);
        cp16(&Bs[0][b_k0][b_c],     Bm + (size_t)b_k0 * N + n0 + b_c);
        cp16(&Bs[0][b_k0 + 8][b_c], Bm + (size_t)(b_k0 + 8) * N + n0 + b_c);
        CP_COMMIT();
    }

    const int nchunk = K / KC;
    for (int ci = 0; ci < nchunk; ci++) {
        const int s = ci & 1;
        if (ci + 1 < nchunk) {
            const int kn = (ci + 1) * KC;
            cp16(&As[s ^ 1][a_r][a_c],      Aptr0 + kn);
            cp16(&As[s ^ 1][a_r + 64][a_c], Aptr1 + kn);
            cp16(&Bs[s ^ 1][b_k0][b_c],     Bm + (size_t)(kn + b_k0) * N + n0 + b_c);
            cp16(&Bs[s ^ 1][b_k0 + 8][b_c], Bm + (size_t)(kn + b_k0 + 8) * N + n0 + b_c);
            CP_COMMIT();
            CP_WAIT(1);
        } else {
            CP_WAIT(0);
        }
        __syncthreads();

        #pragma unroll
        for (int ks = 0; ks < 2; ks++) {
            const int k0 = ks * 8;
            uint32_t af[4][4], bf[4][2];
            #pragma unroll
            for (int mt = 0; mt < 4; mt++) {
                int r = wm * 64 + mt * 16 + (lane >> 2);
                int kc = k0 + (lane & 3);
                af[mt][0] = f2tf32(As[s][r][kc]);
                af[mt][1] = f2tf32(As[s][r + 8][kc]);
                af[mt][2] = f2tf32(As[s][r][kc + 4]);
                af[mt][3] = f2tf32(As[s][r + 8][kc + 4]);
            }
            #pragma unroll
            for (int nt = 0; nt < 4; nt++) {
                int cn = wn * 32 + nt * 8 + (lane >> 2);
                int kc = k0 + (lane & 3);
                bf[nt][0] = f2tf32(Bs[s][kc][cn]);
                bf[nt][1] = f2tf32(Bs[s][kc + 4][cn]);
            }
            #pragma unroll
            for (int mt = 0; mt < 4; mt++)
                #pragma unroll
                for (int nt = 0; nt < 4; nt++)
                    mma_tf32(acc[mt][nt], af[mt], bf[nt]);
        }
        __syncthreads();
    }

    // -------- epilogues --------
    if (MODE == 0) {
        #pragma unroll
        for (int mt = 0; mt < 4; mt++) {
            int r = m0 + wm * 64 + mt * 16 + (lane >> 2);
            #pragma unroll
            for (int nt = 0; nt < 4; nt++) {
                int cc = n0 + wn * 32 + nt * 8 + (lane & 3) * 2;
                *(float2*)(C + (size_t)r * N + cc)       = make_float2(acc[mt][nt][0], acc[mt][nt][1]);
                *(float2*)(C + (size_t)(r + 8) * N + cc) = make_float2(acc[mt][nt][2], acc[mt][nt][3]);
            }
        }
    } else {
        const bool doRope = (MODE == 1) || !isV;
        #pragma unroll
        for (int mt = 0; mt < 4; mt++) {
            int r = m0 + wm * 64 + mt * 16 + (lane >> 2);
            int b = r >> 11;                 // r / S_
            int sA = r & (S_ - 1);
            int sB = sA + 8;
            #pragma unroll
            for (int nt = 0; nt < 4; nt++) {
                int cc = n0 + wn * 32 + nt * 8 + (lane & 3) * 2;
                int h  = cc >> 7;
                int dd = cc & (D_ - 1);
                int p  = dd >> 1;

                float a0 = acc[mt][nt][0], a1 = acc[mt][nt][1];
                float a2 = acc[mt][nt][2], a3 = acc[mt][nt][3];
                float o0, o1, o2, o3;
                if (doRope) {
                    float2 csA = ((const float2*)fc)[(size_t)sA * 64 + p];
                    float2 csB = ((const float2*)fc)[(size_t)sB * 64 + p];
                    o0 = a0 * csA.x - a1 * csA.y;
                    o1 = a0 * csA.y + a1 * csA.x;
                    o2 = a2 * csB.x - a3 * csB.y;
                    o3 = a2 * csB.y + a3 * csB.x;
                } else {
                    o0 = a0; o1 = a1; o2 = a2; o3 = a3;
                }
                if (MODE == 1) { o0 *= SCALE_; o1 *= SCALE_; o2 *= SCALE_; o3 *= SCALE_; }

                uint2 u0 = make_uint2(f2tf32(o0), f2tf32(o1));
                uint2 u1 = make_uint2(f2tf32(o2), f2tf32(o3));

                if (MODE == 1) {
                    size_t i0 = ((size_t)(b * HQ_ + h) * S_ + sA) * D_ + dd;
                    size_t i1 = ((size_t)(b * HQ_ + h) * S_ + sB) * D_ + dd;
                    *(uint2*)(Ok + i0) = u0;
                    *(uint2*)(Ok + i1) = u1;
                } else {
                    int posA = ip[sA], posB = ip[sB];
                    uint32_t* Od = isV ? Ov : Ok;
                    size_t i0 = ((size_t)(b * HKV_ + h) * S_ + posA) * D_ + dd;
                    size_t i1 = ((size_t)(b * HKV_ + h) * S_ + posB) * D_ + dd;
                    *(uint2*)(Od + i0) = u0;
                    *(uint2*)(Od + i1) = u1;
                }
            }
        }
    }
}

// ---------------------------------------------------------------------------
// Fused flash attention, tf32-preconverted inputs (no cvt in hot loop).
// One block = one (b,h) x 128-row Q tile; 8 warps x 16 rows; KV 64-row tiles
// double buffered; online softmax in registers.
// ---------------------------------------------------------------------------
#define FSTR 132

__device__ __forceinline__ void fa_load_kv(
    uint32_t* Ks, uint32_t* Vs, int stage,
    const uint32_t* __restrict__ Kp, const uint32_t* __restrict__ Vp, int tid)
{
    uint32_t* kd = Ks + stage * 64 * FSTR;
    uint32_t* vd = Vs + stage * 64 * FSTR;
    #pragma unroll
    for (int i = 0; i < 8; i++) {
        int e = i * 256 + tid;
        int r = e >> 5, c4 = (e & 31) * 4;
        cp16(kd + r * FSTR + c4, Kp + (size_t)r * D_ + c4);
        cp16(vd + r * FSTR + c4, Vp + (size_t)r * D_ + c4);
    }
}

__global__ __launch_bounds__(256, 1) void flash_tf32(
    const uint32_t* __restrict__ Qb, const uint32_t* __restrict__ Kc,
    const uint32_t* __restrict__ Vc, float* __restrict__ AO)
{
    extern __shared__ uint32_t smbuf[];
    uint32_t* Qs = smbuf;                         // [128][FSTR]
    uint32_t* Ks = smbuf + 128 * FSTR;            // [2][64][FSTR]
    uint32_t* Vs = smbuf + 128 * FSTR + 2 * 64 * FSTR;

    const int qt = (S_ / 128 - 1) - blockIdx.x;   // heavy tiles first
    const int bh = blockIdx.y;
    const int b = bh / HQ_, h = bh % HQ_;
    const int kvh = h / (HQ_ / HKV_);
    const int m0 = qt * 128;

    const int tid = threadIdx.x, lane = tid & 31, warp = tid >> 5;
    const int g = lane >> 2, t = lane & 3;

    const uint32_t* Qbase = Qb + (size_t)(b * HQ_ + h) * S_ * D_ + (size_t)m0 * D_;
    const uint32_t* Kbase = Kc + (size_t)(b * HKV_ + kvh) * S_ * D_;
    const uint32_t* Vbase = Vc + (size_t)(b * HKV_ + kvh) * S_ * D_;

    #pragma unroll
    for (int i = 0; i < 16; i++) {
        int e = i * 256 + tid;
        int r = e >> 5, c4 = (e & 31) * 4;
        cp16(Qs + r * FSTR + c4, Qbase + (size_t)r * D_ + c4);
    }
    CP_COMMIT();

    const int nkt = 2 * qt + 2;
    fa_load_kv(Ks, Vs, 0, Kbase, Vbase, tid);
    CP_COMMIT();

    uint32_t qf[16][4];
    float Oacc[16][4] = {};
    float mrow0 = -FLT_MAX, mrow1 = -FLT_MAX;
    float lrow0 = 0.f, lrow1 = 0.f;

    const int srcA = (lane & ~3) | (t >> 1);
    const int srcB = srcA + 2;
    const bool odd = (t & 1);

    for (int kt = 0; kt < nkt; kt++) {
        const int s = kt & 1;
        if (kt + 1 < nkt) {
            fa_load_kv(Ks, Vs, s ^ 1, Kbase + (size_t)(kt + 1) * 64 * D_,
                       Vbase + (size_t)(kt + 1) * 64 * D_, tid);
            CP_COMMIT();
            CP_WAIT(1);
        } else {
            CP_WAIT(0);
        }
        __syncthreads();

        if (kt == 0) {
            #pragma unroll
            for (int ks = 0; ks < 16; ks++) {
                int r = warp * 16 + g, kc = ks * 8 + t;
                qf[ks][0] = Qs[r * FSTR + kc];
                qf[ks][1] = Qs[(r + 8) * FSTR + kc];
                qf[ks][2] = Qs[r * FSTR + kc + 4];
                qf[ks][3] = Qs[(r + 8) * FSTR + kc + 4];
            }
        }

        const uint32_t* ks_base = Ks + s * 64 * FSTR;
        const uint32_t* vs_base = Vs + s * 64 * FSTR;

        // ---- S = Q K^T (Q pre-scaled by SCALE_) ----
        float sc[8][4];
        #pragma unroll
        for (int nf = 0; nf < 8; nf++)
            sc[nf][0] = sc[nf][1] = sc[nf][2] = sc[nf][3] = 0.f;
        #pragma unroll
        for (int ks = 0; ks < 16; ks++) {
            #pragma unroll
            for (int nf = 0; nf < 8; nf++) {
                uint32_t bb[2];
                const uint32_t* kp = ks_base + (nf * 8 + g) * FSTR + ks * 8 + t;
                bb[0] = kp[0];
                bb[1] = kp[4];
                mma_tf32(sc[nf], qf[ks], bb);
            }
        }

        // ---- causal mask (diagonal tiles only) ----
        const int r0 = m0 + warp * 16 + g;
        const int r1 = r0 + 8;
        if (kt >= 2 * qt) {
            #pragma unroll
            for (int nf = 0; nf < 8; nf++) {
                int c0 = kt * 64 + nf * 8 + 2 * t;
                if (c0     > r0) sc[nf][0] = -FLT_MAX;
                if (c0 + 1 > r0) sc[nf][1] = -FLT_MAX;
                if (c0     > r1) sc[nf][2] = -FLT_MAX;
                if (c0 + 1 > r1) sc[nf][3] = -FLT_MAX;
            }
        }

        // ---- online softmax ----
        float mx0 = -FLT_MAX, mx1 = -FLT_MAX;
        #pragma unroll
        for (int nf = 0; nf < 8; nf++) {
            mx0 = fmaxf(mx0, fmaxf(sc[nf][0], sc[nf][1]));
            mx1 = fmaxf(mx1, fmaxf(sc[nf][2], sc[nf][3]));
        }
        mx0 = fmaxf(mx0, __shfl_xor_sync(0xffffffffu, mx0, 1));
        mx0 = fmaxf(mx0, __shfl_xor_sync(0xffffffffu, mx0, 2));
        mx1 = fmaxf(mx1, __shfl_xor_sync(0xffffffffu, mx1, 1));
        mx1 = fmaxf(mx1, __shfl_xor_sync(0xffffffffu, mx1, 2));

        float mnew0 = fmaxf(mrow0, mx0), mnew1 = fmaxf(mrow1, mx1);
        float f0 = __expf(mrow0 - mnew0), f1 = __expf(mrow1 - mnew1);
        mrow0 = mnew0; mrow1 = mnew1;

        float rs0 = 0.f, rs1 = 0.f;
        #pragma unroll
        for (int nf = 0; nf < 8; nf++) {
            sc[nf][0] = __expf(sc[nf][0] - mnew0);
            sc[nf][1] = __expf(sc[nf][1] - mnew0);
            sc[nf][2] = __expf(sc[nf][2] - mnew1);
            sc[nf][3] = __expf(sc[nf][3] - mnew1);
            rs0 += sc[nf][0] + sc[nf][1];
            rs1 += sc[nf][2] + sc[nf][3];
        }
        rs0 += __shfl_xor_sync(0xffffffffu, rs0, 1);
        rs0 += __shfl_xor_sync(0xffffffffu, rs0, 2);
        rs1 += __shfl_xor_sync(0xffffffffu, rs1, 1);
        rs1 += __shfl_xor_sync(0xffffffffu, rs1, 2);
        lrow0 = lrow0 * f0 + rs0;
        lrow1 = lrow1 * f1 + rs1;

        #pragma unroll
        for (int nf2 = 0; nf2 < 16; nf2++) {
            Oacc[nf2][0] *= f0; Oacc[nf2][1] *= f0;
            Oacc[nf2][2] *= f1; Oacc[nf2][3] *= f1;
        }

        // ---- O += P V ----
        #pragma unroll
        for (int kc2 = 0; kc2 < 8; kc2++) {
            float vA0 = __shfl_sync(0xffffffffu, sc[kc2][0], srcA);
            float vA1 = __shfl_sync(0xffffffffu, sc[kc2][1], srcA);
            float vA2 = __shfl_sync(0xffffffffu, sc[kc2][2], srcA);
            float vA3 = __shfl_sync(0xffffffffu, sc[kc2][3], srcA);
            float vB0 = __shfl_sync(0xffffffffu, sc[kc2][0], srcB);
            float vB1 = __shfl_sync(0xffffffffu, sc[kc2][1], srcB);
            float vB2 = __shfl_sync(0xffffffffu, sc[kc2][2], srcB);
            float vB3 = __shfl_sync(0xffffffffu, sc[kc2][3], srcB);
            uint32_t aP[4];
            aP[0] = f2tf32(odd ? vA1 : vA0);
            aP[1] = f2tf32(odd ? vA3 : vA2);
            aP[2] = f2tf32(odd ? vB1 : vB0);
            aP[3] = f2tf32(odd ? vB3 : vB2);

            #pragma unroll
            for (int nf2 = 0; nf2 < 16; nf2++) {
                uint32_t bv[2];
                const uint32_t* vp = vs_base + (kc2 * 8 + t) * FSTR + nf2 * 8 + g;
                bv[0] = vp[0];
                bv[1] = vp[4 * FSTR];
                mma_tf32(Oacc[nf2], aP, bv);
            }
        }

        __syncthreads();
    }

    const float inv0 = 1.0f / lrow0, inv1 = 1.0f / lrow1;
    const int r0 = m0 + warp * 16 + g;
    #pragma unroll
    for (int nf2 = 0; nf2 < 16; nf2++) {
        int cc = h * D_ + nf2 * 8 + 2 * t;
        float* C0 = AO + (size_t)(b * S_ + r0) * (HQ_ * D_) + cc;
        float* C1 = AO + (size_t)(b * S_ + r0 + 8) * (HQ_ * D_) + cc;
        *(float2*)C0 = make_float2(Oacc[nf2][0] * inv0, Oacc[nf2][1] * inv0);
        *(float2*)C1 = make_float2(Oacc[nf2][2] * inv1, Oacc[nf2][3] * inv1);
    }
}

#define FLASH_SMEM ((128 * FSTR + 4 * 64 * FSTR) * 4)

// ---------------------------------------------------------------------------
// kernel_launch
// ---------------------------------------------------------------------------
extern "C" void kernel_launch(void* const* d_in, const int* in_sizes, int n_in,
                              void* d_out, int out_size) {
    const float* x  = (const float*)d_in[0];
    const int*   ip = (const int*)  d_in[1];
    const float* fc = (const float*)d_in[2];
    const float* wq = (const float*)d_in[3];
    const float* wk = (const float*)d_in[4];
    const float* wv = (const float*)d_in[5];
    const float* wo = (const float*)d_in[6];
    float* out = (float*)d_out;

    uint32_t *Qb, *Kc, *Vc;
    float *AO;
    cudaGetSymbolAddress((void**)&Qb, g_Qb);
    cudaGetSymbolAddress((void**)&Kc, g_Kc);
    cudaGetSymbolAddress((void**)&Vc, g_Vc);
    cudaGetSymbolAddress((void**)&AO, g_AO);

    static int smem_set = 0;
    if (!smem_set) {
        cudaFuncSetAttribute(flash_tf32, cudaFuncAttributeMaxDynamicSharedMemorySize, FLASH_SMEM);
        smem_set = 1;
    }

    // 1) Q projection with fused RoPE+scale+transpose (tf32 bits out)
    gemm_ep<1><<<dim3(E_ / 128, M_ / 128), 256>>>(
        x, wq, nullptr, nullptr, Qb, nullptr, fc, nullptr, M_, HQ_ * D_, E_);

    // 2) K+V projections fused, RoPE/copy + cache scatter (tf32 bits out)
    gemm_ep<2><<<dim3(16, M_ / 128), 256>>>(
        x, wk, wv, nullptr, Kc, Vc, fc, ip, M_, HKV_ * D_, E_);

    // 3) Fused flash attention
    flash_tf32<<<dim3(S_ / 128, B_ * HQ_), 256, FLASH_SMEM>>>(Qb, Kc, Vc, AO);

    // 4) Output projection
    gemm_ep<0><<<dim3(E_ / 128, M_ / 128), 256>>>(
        AO, wo, nullptr, out, nullptr, nullptr, nullptr, nullptr, M_, E_, E_);
}

// round 6
// speedup vs baseline: 5.5926x; 1.0247x over previous
#include <cuda_runtime.h>
#include <cuda_bf16.h>
#include <float.h>
#include <math.h>
#include <stdint.h>

// Problem constants
#define B_   2
#define S_   2048
#define E_   4096
#define HQ_  32
#define HKV_ 8
#define D_   128
#define M_   (B_ * S_)          // 4096
#define SCALE_ 0.015625f        // 1/sqrt(4096)

// ---------------------------------------------------------------------------
// Scratch (tf32 bit patterns unless noted)
// ---------------------------------------------------------------------------
__device__ uint32_t g_xT [(size_t)M_ * E_];              // x   as tf32 bits
__device__ uint32_t g_wqT[(size_t)E_ * (HQ_ * D_)];      // wq
__device__ uint32_t g_wkT[(size_t)E_ * (HKV_ * D_)];     // wk
__device__ uint32_t g_wvT[(size_t)E_ * (HKV_ * D_)];     // wv
__device__ uint32_t g_woT[(size_t)(HQ_ * D_) * E_];      // wo
__device__ uint32_t g_Qb [(size_t)B_ * HQ_ * S_ * D_];   // roped+scaled Q
__device__ uint32_t g_Kc [(size_t)B_ * HKV_ * S_ * D_];  // roped K (cache layout)
__device__ uint32_t g_Vc [(size_t)B_ * HKV_ * S_ * D_];  // V (cache layout)
__device__ uint32_t g_AO [(size_t)M_ * (HQ_ * D_)];      // attn out, tf32 bits

// ---------------------------------------------------------------------------
// tf32 helpers
// ---------------------------------------------------------------------------
__device__ __forceinline__ uint32_t f2tf32(float f) {
    uint32_t r;
    asm volatile("cvt.rna.tf32.f32 %0, %1;" : "=r"(r) : "f"(f));
    return r;
}
__device__ __forceinline__ void mma_tf32(float* c, const uint32_t* a, const uint32_t* b) {
    asm volatile(
        "mma.sync.aligned.m16n8k8.row.col.f32.tf32.tf32.f32 "
        "{%0,%1,%2,%3},{%4,%5,%6,%7},{%8,%9},{%0,%1,%2,%3};"
        : "+f"(c[0]), "+f"(c[1]), "+f"(c[2]), "+f"(c[3])
        : "r"(a[0]), "r"(a[1]), "r"(a[2]), "r"(a[3]), "r"(b[0]), "r"(b[1]));
}
__device__ __forceinline__ void cp16(void* smem, const void* gmem) {
    uint32_t s = (uint32_t)__cvta_generic_to_shared(smem);
    asm volatile("cp.async.cg.shared.global [%0], [%1], 16;\n" :: "r"(s), "l"(gmem));
}
#define CP_COMMIT() asm volatile("cp.async.commit_group;\n" ::: "memory")
#define CP_WAIT(n)  asm volatile("cp.async.wait_group %0;\n" :: "n"(n) : "memory")

// ---------------------------------------------------------------------------
// Pre-pass: fp32 -> tf32 bits, vectorized
// ---------------------------------------------------------------------------
__global__ void cvt_tf32_arr(const float4* __restrict__ in, uint4* __restrict__ out, int n4) {
    int i = blockIdx.x * 256 + threadIdx.x;
    if (i < n4) {
        float4 v = in[i];
        out[i] = make_uint4(f2tf32(v.x), f2tf32(v.y), f2tf32(v.z), f2tf32(v.w));
    }
}

#define KC 16
#define AS_STRIDE 20
#define BS_STRIDE 136

// ---------------------------------------------------------------------------
// tf32 GEMM on pre-converted uint32 inputs, fused epilogues.
//   MODE 0: fp32 C = A @ B                       (out-projection)
//   MODE 1: Q proj: RoPE + *SCALE_ + transpose -> Ok (tf32 bits)
//   MODE 2: K+V fused: blockIdx.x<8 K (RoPE+scatter) -> Ok, else V -> Ov
// ---------------------------------------------------------------------------
template<int MODE>
__global__ __launch_bounds__(256, 2) void gemm_ep(
    const uint32_t* __restrict__ A, const uint32_t* __restrict__ Bk, const uint32_t* __restrict__ Bv,
    float* __restrict__ C, uint32_t* __restrict__ Ok, uint32_t* __restrict__ Ov,
    const float* __restrict__ fc, const int* __restrict__ ip,
    int M, int N, int K)
{
    __shared__ uint32_t As[2][128][AS_STRIDE];
    __shared__ uint32_t Bs[2][KC][BS_STRIDE];
    const int tid = threadIdx.x;
    const int lane = tid & 31, warp = tid >> 5;
    const int wm = warp & 1, wn = warp >> 1;
    const int m0 = blockIdx.y * 128;

    const uint32_t* Bm;
    int n0;
    bool isV = false;
    if (MODE == 2) {
        if (blockIdx.x < 8) { Bm = Bk; n0 = blockIdx.x * 128; }
        else                { Bm = Bv; n0 = (blockIdx.x - 8) * 128; isV = true; }
    } else {
        Bm = Bk; n0 = blockIdx.x * 128;
    }

    float acc[4][4][4] = {};

    const int a_r = tid >> 2, a_c = (tid & 3) * 4;
    const int b_k0 = tid >> 5, b_c = (tid & 31) * 4;

    const uint32_t* Aptr0 = A + (size_t)(m0 + a_r) * K + a_c;
    const uint32_t* Aptr1 = A + (size_t)(m0 + a_r + 64) * K + a_c;

    {
        cp16(&As[0][a_r][a_c],      Aptr0);
        cp16(&As[0][a_r + 64][a_c], Aptr1);
        cp16(&Bs[0][b_k0][b_c],     Bm + (size_t)b_k0 * N + n0 + b_c);
        cp16(&Bs[0][b_k0 + 8][b_c], Bm + (size_t)(b_k0 + 8) * N + n0 + b_c);
        CP_COMMIT();
    }

    const int nchunk = K / KC;
    for (int ci = 0; ci < nchunk; ci++) {
        const int s = ci & 1;
        if (ci + 1 < nchunk) {
            const int kn = (ci + 1) * KC;
            cp16(&As[s ^ 1][a_r][a_c],      Aptr0 + kn);
            cp16(&As[s ^ 1][a_r + 64][a_c], Aptr1 + kn);
            cp16(&Bs[s ^ 1][b_k0][b_c],     Bm + (size_t)(kn + b_k0) * N + n0 + b_c);
            cp16(&Bs[s ^ 1][b_k0 + 8][b_c], Bm + (size_t)(kn + b_k0 + 8) * N + n0 + b_c);
            CP_COMMIT();
            CP_WAIT(1);
        } else {
            CP_WAIT(0);
        }
        __syncthreads();

        #pragma unroll
        for (int ks = 0; ks < 2; ks++) {
            const int k0 = ks * 8;
            uint32_t af[4][4], bf[4][2];
            #pragma unroll
            for (int mt = 0; mt < 4; mt++) {
                int r = wm * 64 + mt * 16 + (lane >> 2);
                int kc = k0 + (lane & 3);
                af[mt][0] = As[s][r][kc];
                af[mt][1] = As[s][r + 8][kc];
                af[mt][2] = As[s][r][kc + 4];
                af[mt][3] = As[s][r + 8][kc + 4];
            }
            #pragma unroll
            for (int nt = 0; nt < 4; nt++) {
                int cn = wn * 32 + nt * 8 + (lane >> 2);
                int kc = k0 + (lane & 3);
                bf[nt][0] = Bs[s][kc][cn];
                bf[nt][1] = Bs[s][kc + 4][cn];
            }
            #pragma unroll
            for (int mt = 0; mt < 4; mt++)
                #pragma unroll
                for (int nt = 0; nt < 4; nt++)
                    mma_tf32(acc[mt][nt], af[mt], bf[nt]);
        }
        __syncthreads();
    }

    // -------- epilogues --------
    if (MODE == 0) {
        #pragma unroll
        for (int mt = 0; mt < 4; mt++) {
            int r = m0 + wm * 64 + mt * 16 + (lane >> 2);
            #pragma unroll
            for (int nt = 0; nt < 4; nt++) {
                int cc = n0 + wn * 32 + nt * 8 + (lane & 3) * 2;
                *(float2*)(C + (size_t)r * N + cc)       = make_float2(acc[mt][nt][0], acc[mt][nt][1]);
                *(float2*)(C + (size_t)(r + 8) * N + cc) = make_float2(acc[mt][nt][2], acc[mt][nt][3]);
            }
        }
    } else {
        const bool doRope = (MODE == 1) || !isV;
        #pragma unroll
        for (int mt = 0; mt < 4; mt++) {
            int r = m0 + wm * 64 + mt * 16 + (lane >> 2);
            int b = r >> 11;
            int sA = r & (S_ - 1);
            int sB = sA + 8;
            #pragma unroll
            for (int nt = 0; nt < 4; nt++) {
                int cc = n0 + wn * 32 + nt * 8 + (lane & 3) * 2;
                int h  = cc >> 7;
                int dd = cc & (D_ - 1);
                int p  = dd >> 1;

                float a0 = acc[mt][nt][0], a1 = acc[mt][nt][1];
                float a2 = acc[mt][nt][2], a3 = acc[mt][nt][3];
                float o0, o1, o2, o3;
                if (doRope) {
                    float2 csA = ((const float2*)fc)[(size_t)sA * 64 + p];
                    float2 csB = ((const float2*)fc)[(size_t)sB * 64 + p];
                    o0 = a0 * csA.x - a1 * csA.y;
                    o1 = a0 * csA.y + a1 * csA.x;
                    o2 = a2 * csB.x - a3 * csB.y;
                    o3 = a2 * csB.y + a3 * csB.x;
                } else {
                    o0 = a0; o1 = a1; o2 = a2; o3 = a3;
                }
                if (MODE == 1) { o0 *= SCALE_; o1 *= SCALE_; o2 *= SCALE_; o3 *= SCALE_; }

                uint2 u0 = make_uint2(f2tf32(o0), f2tf32(o1));
                uint2 u1 = make_uint2(f2tf32(o2), f2tf32(o3));

                if (MODE == 1) {
                    size_t i0 = ((size_t)(b * HQ_ + h) * S_ + sA) * D_ + dd;
                    size_t i1 = ((size_t)(b * HQ_ + h) * S_ + sB) * D_ + dd;
                    *(uint2*)(Ok + i0) = u0;
                    *(uint2*)(Ok + i1) = u1;
                } else {
                    int posA = ip[sA], posB = ip[sB];
                    uint32_t* Od = isV ? Ov : Ok;
                    size_t i0 = ((size_t)(b * HKV_ + h) * S_ + posA) * D_ + dd;
                    size_t i1 = ((size_t)(b * HKV_ + h) * S_ + posB) * D_ + dd;
                    *(uint2*)(Od + i0) = u0;
                    *(uint2*)(Od + i1) = u1;
                }
            }
        }
    }
}

// ---------------------------------------------------------------------------
// Fused flash attention (tf32 inputs/outputs as bits)
// ---------------------------------------------------------------------------
#define FSTR 132

__device__ __forceinline__ void fa_load_kv(
    uint32_t* Ks, uint32_t* Vs, int stage,
    const uint32_t* __restrict__ Kp, const uint32_t* __restrict__ Vp, int tid)
{
    uint32_t* kd = Ks + stage * 64 * FSTR;
    uint32_t* vd = Vs + stage * 64 * FSTR;
    #pragma unroll
    for (int i = 0; i < 8; i++) {
        int e = i * 256 + tid;
        int r = e >> 5, c4 = (e & 31) * 4;
        cp16(kd + r * FSTR + c4, Kp + (size_t)r * D_ + c4);
        cp16(vd + r * FSTR + c4, Vp + (size_t)r * D_ + c4);
    }
}

__global__ __launch_bounds__(256, 1) void flash_tf32(
    const uint32_t* __restrict__ Qb, const uint32_t* __restrict__ Kc,
    const uint32_t* __restrict__ Vc, uint32_t* __restrict__ AO)
{
    extern __shared__ uint32_t smbuf[];
    uint32_t* Qs = smbuf;
    uint32_t* Ks = smbuf + 128 * FSTR;
    uint32_t* Vs = smbuf + 128 * FSTR + 2 * 64 * FSTR;

    const int qt = (S_ / 128 - 1) - blockIdx.x;
    const int bh = blockIdx.y;
    const int b = bh / HQ_, h = bh % HQ_;
    const int kvh = h / (HQ_ / HKV_);
    const int m0 = qt * 128;

    const int tid = threadIdx.x, lane = tid & 31, warp = tid >> 5;
    const int g = lane >> 2, t = lane & 3;

    const uint32_t* Qbase = Qb + (size_t)(b * HQ_ + h) * S_ * D_ + (size_t)m0 * D_;
    const uint32_t* Kbase = Kc + (size_t)(b * HKV_ + kvh) * S_ * D_;
    const uint32_t* Vbase = Vc + (size_t)(b * HKV_ + kvh) * S_ * D_;

    #pragma unroll
    for (int i = 0; i < 16; i++) {
        int e = i * 256 + tid;
        int r = e >> 5, c4 = (e & 31) * 4;
        cp16(Qs + r * FSTR + c4, Qbase + (size_t)r * D_ + c4);
    }
    CP_COMMIT();

    const int nkt = 2 * qt + 2;
    fa_load_kv(Ks, Vs, 0, Kbase, Vbase, tid);
    CP_COMMIT();

    uint32_t qf[16][4];
    float Oacc[16][4] = {};
    float mrow0 = -FLT_MAX, mrow1 = -FLT_MAX;
    float lrow0 = 0.f, lrow1 = 0.f;

    const int srcA = (lane & ~3) | (t >> 1);
    const int srcB = srcA + 2;
    const bool odd = (t & 1);

    for (int kt = 0; kt < nkt; kt++) {
        const int s = kt & 1;
        if (kt + 1 < nkt) {
            fa_load_kv(Ks, Vs, s ^ 1, Kbase + (size_t)(kt + 1) * 64 * D_,
                       Vbase + (size_t)(kt + 1) * 64 * D_, tid);
            CP_COMMIT();
            CP_WAIT(1);
        } else {
            CP_WAIT(0);
        }
        __syncthreads();

        if (kt == 0) {
            #pragma unroll
            for (int ks = 0; ks < 16; ks++) {
                int r = warp * 16 + g, kc = ks * 8 + t;
                qf[ks][0] = Qs[r * FSTR + kc];
                qf[ks][1] = Qs[(r + 8) * FSTR + kc];
                qf[ks][2] = Qs[r * FSTR + kc + 4];
                qf[ks][3] = Qs[(r + 8) * FSTR + kc + 4];
            }
        }

        const uint32_t* ks_base = Ks + s * 64 * FSTR;
        const uint32_t* vs_base = Vs + s * 64 * FSTR;

        float sc[8][4];
        #pragma unroll
        for (int nf = 0; nf < 8; nf++)
            sc[nf][0] = sc[nf][1] = sc[nf][2] = sc[nf][3] = 0.f;
        #pragma unroll
        for (int ks = 0; ks < 16; ks++) {
            #pragma unroll
            for (int nf = 0; nf < 8; nf++) {
                uint32_t bb[2];
                const uint32_t* kp = ks_base + (nf * 8 + g) * FSTR + ks * 8 + t;
                bb[0] = kp[0];
                bb[1] = kp[4];
                mma_tf32(sc[nf], qf[ks], bb);
            }
        }

        const int r0 = m0 + warp * 16 + g;
        const int r1 = r0 + 8;
        if (kt >= 2 * qt) {
            #pragma unroll
            for (int nf = 0; nf < 8; nf++) {
                int c0 = kt * 64 + nf * 8 + 2 * t;
                if (c0     > r0) sc[nf][0] = -FLT_MAX;
                if (c0 + 1 > r0) sc[nf][1] = -FLT_MAX;
                if (c0     > r1) sc[nf][2] = -FLT_MAX;
                if (c0 + 1 > r1) sc[nf][3] = -FLT_MAX;
            }
        }

        float mx0 = -FLT_MAX, mx1 = -FLT_MAX;
        #pragma unroll
        for (int nf = 0; nf < 8; nf++) {
            mx0 = fmaxf(mx0, fmaxf(sc[nf][0], sc[nf][1]));
            mx1 = fmaxf(mx1, fmaxf(sc[nf][2], sc[nf][3]));
        }
        mx0 = fmaxf(mx0, __shfl_xor_sync(0xffffffffu, mx0, 1));
        mx0 = fmaxf(mx0, __shfl_xor_sync(0xffffffffu, mx0, 2));
        mx1 = fmaxf(mx1, __shfl_xor_sync(0xffffffffu, mx1, 1));
        mx1 = fmaxf(mx1, __shfl_xor_sync(0xffffffffu, mx1, 2));

        float mnew0 = fmaxf(mrow0, mx0), mnew1 = fmaxf(mrow1, mx1);
        float f0 = __expf(mrow0 - mnew0), f1 = __expf(mrow1 - mnew1);
        mrow0 = mnew0; mrow1 = mnew1;

        float rs0 = 0.f, rs1 = 0.f;
        #pragma unroll
        for (int nf = 0; nf < 8; nf++) {
            sc[nf][0] = __expf(sc[nf][0] - mnew0);
            sc[nf][1] = __expf(sc[nf][1] - mnew0);
            sc[nf][2] = __expf(sc[nf][2] - mnew1);
            sc[nf][3] = __expf(sc[nf][3] - mnew1);
            rs0 += sc[nf][0] + sc[nf][1];
            rs1 += sc[nf][2] + sc[nf][3];
        }
        rs0 += __shfl_xor_sync(0xffffffffu, rs0, 1);
        rs0 += __shfl_xor_sync(0xffffffffu, rs0, 2);
        rs1 += __shfl_xor_sync(0xffffffffu, rs1, 1);
        rs1 += __shfl_xor_sync(0xffffffffu, rs1, 2);
        lrow0 = lrow0 * f0 + rs0;
        lrow1 = lrow1 * f1 + rs1;

        #pragma unroll
        for (int nf2 = 0; nf2 < 16; nf2++) {
            Oacc[nf2][0] *= f0; Oacc[nf2][1] *= f0;
            Oacc[nf2][2] *= f1; Oacc[nf2][3] *= f1;
        }

        #pragma unroll
        for (int kc2 = 0; kc2 < 8; kc2++) {
            float vA0 = __shfl_sync(0xffffffffu, sc[kc2][0], srcA);
            float vA1 = __shfl_sync(0xffffffffu, sc[kc2][1], srcA);
            float vA2 = __shfl_sync(0xffffffffu, sc[kc2][2], srcA);
            float vA3 = __shfl_sync(0xffffffffu, sc[kc2][3], srcA);
            float vB0 = __shfl_sync(0xffffffffu, sc[kc2][0], srcB);
            float vB1 = __shfl_sync(0xffffffffu, sc[kc2][1], srcB);
            float vB2 = __shfl_sync(0xffffffffu, sc[kc2][2], srcB);
            float vB3 = __shfl_sync(0xffffffffu, sc[kc2][3], srcB);
            uint32_t aP[4];
            aP[0] = f2tf32(odd ? vA1 : vA0);
            aP[1] = f2tf32(odd ? vA3 : vA2);
            aP[2] = f2tf32(odd ? vB1 : vB0);
            aP[3] = f2tf32(odd ? vB3 : vB2);

            #pragma unroll
            for (int nf2 = 0; nf2 < 16; nf2++) {
                uint32_t bv[2];
                const uint32_t* vp = vs_base + (kc2 * 8 + t) * FSTR + nf2 * 8 + g;
                bv[0] = vp[0];
                bv[1] = vp[4 * FSTR];
                mma_tf32(Oacc[nf2], aP, bv);
            }
        }

        __syncthreads();
    }

    // normalize + store as tf32 bits (feeds out-projection directly)
    const float inv0 = 1.0f / lrow0, inv1 = 1.0f / lrow1;
    const int r0 = m0 + warp * 16 + g;
    #pragma unroll
    for (int nf2 = 0; nf2 < 16; nf2++) {
        int cc = h * D_ + nf2 * 8 + 2 * t;
        uint32_t* C0 = AO + (size_t)(b * S_ + r0) * (HQ_ * D_) + cc;
        uint32_t* C1 = AO + (size_t)(b * S_ + r0 + 8) * (HQ_ * D_) + cc;
        *(uint2*)C0 = make_uint2(f2tf32(Oacc[nf2][0] * inv0), f2tf32(Oacc[nf2][1] * inv0));
        *(uint2*)C1 = make_uint2(f2tf32(Oacc[nf2][2] * inv1), f2tf32(Oacc[nf2][3] * inv1));
    }
}

#define FLASH_SMEM ((128 * FSTR + 4 * 64 * FSTR) * 4)

// ---------------------------------------------------------------------------
// kernel_launch
// ---------------------------------------------------------------------------
extern "C" void kernel_launch(void* const* d_in, const int* in_sizes, int n_in,
                              void* d_out, int out_size) {
    const float* x  = (const float*)d_in[0];
    const int*   ip = (const int*)  d_in[1];
    const float* fc = (const float*)d_in[2];
    const float* wq = (const float*)d_in[3];
    const float* wk = (const float*)d_in[4];
    const float* wv = (const float*)d_in[5];
    const float* wo = (const float*)d_in[6];
    float* out = (float*)d_out;

    uint32_t *xT, *wqT, *wkT, *wvT, *woT, *Qb, *Kc, *Vc, *AO;
    cudaGetSymbolAddress((void**)&xT,  g_xT);
    cudaGetSymbolAddress((void**)&wqT, g_wqT);
    cudaGetSymbolAddress((void**)&wkT, g_wkT);
    cudaGetSymbolAddress((void**)&wvT, g_wvT);
    cudaGetSymbolAddress((void**)&woT, g_woT);
    cudaGetSymbolAddress((void**)&Qb,  g_Qb);
    cudaGetSymbolAddress((void**)&Kc,  g_Kc);
    cudaGetSymbolAddress((void**)&Vc,  g_Vc);
    cudaGetSymbolAddress((void**)&AO,  g_AO);

    static int smem_set = 0;
    if (!smem_set) {
        cudaFuncSetAttribute(flash_tf32, cudaFuncAttributeMaxDynamicSharedMemorySize, FLASH_SMEM);
        smem_set = 1;
    }

    // 0) Pre-convert inputs/weights to tf32 bits
    const int n4_x  = (M_ * E_) / 4;               // 4M
    const int n4_wq = (E_ * HQ_ * D_) / 4;         // 4M
    const int n4_wk = (E_ * HKV_ * D_) / 4;        // 1M
    cvt_tf32_arr<<<(n4_x  + 255) / 256, 256>>>((const float4*)x,  (uint4*)xT,  n4_x);
    cvt_tf32_arr<<<(n4_wq + 255) / 256, 256>>>((const float4*)wq, (uint4*)wqT, n4_wq);
    cvt_tf32_arr<<<(n4_wk + 255) / 256, 256>>>((const float4*)wk, (uint4*)wkT, n4_wk);
    cvt_tf32_arr<<<(n4_wk + 255) / 256, 256>>>((const float4*)wv, (uint4*)wvT, n4_wk);
    cvt_tf32_arr<<<(n4_wq + 255) / 256, 256>>>((const float4*)wo, (uint4*)woT, n4_wq);

    // 1) Q projection (RoPE + scale + transpose fused)
    gemm_ep<1><<<dim3(E_ / 128, M_ / 128), 256>>>(
        xT, wqT, nullptr, nullptr, Qb, nullptr, fc, nullptr, M_, HQ_ * D_, E_);

    // 2) K+V projections fused (RoPE/copy + cache scatter)
    gemm_ep<2><<<dim3(16, M_ / 128), 256>>>(
        xT, wkT, wvT, nullptr, Kc, Vc, fc, ip, M_, HKV_ * D_, E_);

    // 3) Fused flash attention
    flash_tf32<<<dim3(S_ / 128, B_ * HQ_), 256, FLASH_SMEM>>>(Qb, Kc, Vc, AO);

    // 4) Output projection
    gemm_ep<0><<<dim3(E_ / 128, M_ / 128), 256>>>(
        AO, woT, nullptr, out, nullptr, nullptr, nullptr, nullptr, M_, E_, E_);
}

// round 8
// speedup vs baseline: 9.8986x; 1.7699x over previous
#include <cuda_runtime.h>
#include <cuda_fp16.h>
#include <float.h>
#include <math.h>
#include <stdint.h>

// Problem constants
#define B_   2
#define S_   2048
#define E_   4096
#define HQ_  32
#define HKV_ 8
#define D_   128
#define M_   (B_ * S_)          // 4096
#define SCALE_ 0.015625f        // 1/sqrt(4096)

// ---------------------------------------------------------------------------
// Scratch
// ---------------------------------------------------------------------------
__device__ __half   g_xH  [(size_t)M_ * E_];             // x fp16 [M][K]
__device__ __half   g_wqT [(size_t)(HQ_ * D_) * E_];     // wq^T [N][K] fp16
__device__ __half   g_wkT [(size_t)(HKV_ * D_) * E_];    // wk^T
__device__ __half   g_wvT [(size_t)(HKV_ * D_) * E_];    // wv^T
__device__ __half   g_woT [(size_t)E_ * (HQ_ * D_)];     // wo^T
__device__ uint32_t g_Qb  [(size_t)B_ * HQ_ * S_ * D_];  // roped+scaled Q (tf32 bits)
__device__ uint32_t g_Kc  [(size_t)B_ * HKV_ * S_ * D_]; // roped K cache (tf32 bits)
__device__ uint32_t g_Vc  [(size_t)B_ * HKV_ * S_ * D_]; // V cache (tf32 bits)
__device__ __half   g_AO  [(size_t)M_ * (HQ_ * D_)];     // attn out fp16

// ---------------------------------------------------------------------------
// helpers
// ---------------------------------------------------------------------------
__device__ __forceinline__ uint32_t f2tf32(float f) {
    uint32_t r;
    asm volatile("cvt.rna.tf32.f32 %0, %1;" : "=r"(r) : "f"(f));
    return r;
}
__device__ __forceinline__ void mma_tf32(float* c, const uint32_t* a, const uint32_t* b) {
    asm volatile(
        "mma.sync.aligned.m16n8k8.row.col.f32.tf32.tf32.f32 "
        "{%0,%1,%2,%3},{%4,%5,%6,%7},{%8,%9},{%0,%1,%2,%3};"
        : "+f"(c[0]), "+f"(c[1]), "+f"(c[2]), "+f"(c[3])
        : "r"(a[0]), "r"(a[1]), "r"(a[2]), "r"(a[3]), "r"(b[0]), "r"(b[1]));
}
__device__ __forceinline__ void mma_f16(float* c, const uint32_t* a, const uint32_t* b) {
    asm volatile(
        "mma.sync.aligned.m16n8k16.row.col.f32.f16.f16.f32 "
        "{%0,%1,%2,%3},{%4,%5,%6,%7},{%8,%9},{%0,%1,%2,%3};"
        : "+f"(c[0]), "+f"(c[1]), "+f"(c[2]), "+f"(c[3])
        : "r"(a[0]), "r"(a[1]), "r"(a[2]), "r"(a[3]), "r"(b[0]), "r"(b[1]));
}
__device__ __forceinline__ void cp16(void* smem, const void* gmem) {
    uint32_t s = (uint32_t)__cvta_generic_to_shared(smem);
    asm volatile("cp.async.cg.shared.global [%0], [%1], 16;\n" :: "r"(s), "l"(gmem));
}
__device__ __forceinline__ void cp16s(uint32_t saddr, const void* gmem) {
    asm volatile("cp.async.cg.shared.global [%0], [%1], 16;\n" :: "r"(saddr), "l"(gmem));
}
#define CP_COMMIT() asm volatile("cp.async.commit_group;\n" ::: "memory")
#define CP_WAIT(n)  asm volatile("cp.async.wait_group %0;\n" :: "n"(n) : "memory")
__device__ __forceinline__ uint32_t smem_u32(const void* p) {
    return (uint32_t)__cvta_generic_to_shared(p);
}

// ---------------------------------------------------------------------------
// Pre-pass: fp32 -> fp16
// ---------------------------------------------------------------------------
__global__ void cvt_f16_arr(const float4* __restrict__ in, uint2* __restrict__ out, int n4) {
    int i = blockIdx.x * 256 + threadIdx.x;
    if (i < n4) {
        float4 v = in[i];
        __half2 h0 = __floats2half2_rn(v.x, v.y);
        __half2 h1 = __floats2half2_rn(v.z, v.w);
        out[i] = make_uint2(*(uint32_t*)&h0, *(uint32_t*)&h1);
    }
}
// in [Kd][Nd] fp32 -> out [Nd][Kd] fp16
__global__ void cvt_transpose_h(const float* __restrict__ in, __half* __restrict__ out,
                                int Kd, int Nd) {
    __shared__ __half t[32][33];
    int bx = blockIdx.x * 32, by = blockIdx.y * 32;
    int x = threadIdx.x, y = threadIdx.y;          // block (32, 8)
    #pragma unroll
    for (int j = 0; j < 32; j += 8)
        t[y + j][x] = __float2half(in[(size_t)(by + y + j) * Nd + bx + x]);
    __syncthreads();
    #pragma unroll
    for (int j = 0; j < 32; j += 8)
        out[(size_t)(bx + y + j) * Kd + by + x] = t[x][y + j];
}

// ---------------------------------------------------------------------------
// fp16 GEMM: C[M,N] = A[M,K] * Bt[N,K]^T. 128x128 tile, KC=64, dbl-buffered,
// SW128-swizzled smem (conflict-free fragment loads). 8 warps, 64x32 warp tile.
//   MODE 0: fp32 C out                           (out-projection, A = AO fp16)
//   MODE 1: Q proj epilogue (RoPE+scale+transpose) -> Ok tf32 bits
//   MODE 2: K/V proj (blockIdx.x<8: K RoPE+scatter -> Ok; else V -> Ov)
// ---------------------------------------------------------------------------
#define KCH 64                       // k per chunk (halves) = 128 bytes/row
#define TILEB (128 * 128)            // bytes per tile
#define GEMM_DSMEM (4 * TILEB)       // 2 stages x (A + B)

template<int MODE>
__global__ __launch_bounds__(256, 2) void gemm_f16(
    const __half* __restrict__ A, const __half* __restrict__ Btk,
    const __half* __restrict__ Btv,
    float* __restrict__ C, uint32_t* __restrict__ Ok, uint32_t* __restrict__ Ov,
    const float* __restrict__ fc, const int* __restrict__ ip,
    int M, int N, int K)
{
    extern __shared__ __align__(128) uint8_t dynraw[];
    const uint32_t smBase = smem_u32(dynraw);

    const int tid = threadIdx.x;
    const int lane = tid & 31, warp = tid >> 5;
    const int g = lane >> 2, t = lane & 3;
    const int wm = warp & 1, wn = warp >> 1;
    const int m0 = blockIdx.y * 128;

    const __half* Bt;
    int n0;
    bool isV = false;
    if (MODE == 2) {
        if (blockIdx.x < 8) { Bt = Btk; n0 = blockIdx.x * 128; }
        else                { Bt = Btv; n0 = (blockIdx.x - 8) * 128; isV = true; }
    } else {
        Bt = Btk; n0 = blockIdx.x * 128;
    }

    float acc[4][4][4] = {};

    // loader: chunk ck -> stage st. 1024 16B-chunks per tile, 4/thread/tile.
    auto load_chunk = [&](int ck, int st) {
        const uint32_t aB = smBase + st * TILEB;
        const uint32_t bB = smBase + 2 * TILEB + st * TILEB;
        #pragma unroll
        for (int i = 0; i < 4; i++) {
            int c = i * 256 + tid;             // 0..1023
            int row = c >> 3, cp = c & 7;
            uint32_t off = (uint32_t)(row * 128 + ((cp ^ (row & 7)) << 4));
            cp16s(aB + off, A  + (size_t)(m0 + row) * K + ck * KCH + cp * 8);
            cp16s(bB + off, Bt + (size_t)(n0 + row) * K + ck * KCH + cp * 8);
        }
        CP_COMMIT();
    };

    const int nchunk = K / KCH;
    load_chunk(0, 0);

    for (int ci = 0; ci < nchunk; ci++) {
        const int s = ci & 1;
        if (ci + 1 < nchunk) {
            load_chunk(ci + 1, s ^ 1);
            CP_WAIT(1);
        } else {
            CP_WAIT(0);
        }
        __syncthreads();

        const uint32_t* A32 = (const uint32_t*)(dynraw + s * TILEB);
        const uint32_t* B32 = (const uint32_t*)(dynraw + 2 * TILEB + s * TILEB);

        #pragma unroll
        for (int kk = 0; kk < 4; kk++) {       // 4 x k16 per chunk
            const int ch0 = ((2 * kk)     ^ g) << 2;
            const int ch1 = ((2 * kk + 1) ^ g) << 2;
            uint32_t af[4][4], bf[4][2];
            #pragma unroll
            for (int mt = 0; mt < 4; mt++) {
                int w = (wm * 64 + mt * 16 + g) * 32;
                af[mt][0] = A32[w + ch0 + t];
                af[mt][1] = A32[w + 256 + ch0 + t];
                af[mt][2] = A32[w + ch1 + t];
                af[mt][3] = A32[w + 256 + ch1 + t];
            }
            #pragma unroll
            for (int nt = 0; nt < 4; nt++) {
                int w = (wn * 32 + nt * 8 + g) * 32;
                bf[nt][0] = B32[w + ch0 + t];
                bf[nt][1] = B32[w + ch1 + t];
            }
            #pragma unroll
            for (int mt = 0; mt < 4; mt++)
                #pragma unroll
                for (int nt = 0; nt < 4; nt++)
                    mma_f16(acc[mt][nt], af[mt], bf[nt]);
        }
        __syncthreads();
    }

    // -------- epilogues (C fragment layout identical to tf32 path) --------
    if (MODE == 0) {
        #pragma unroll
        for (int mt = 0; mt < 4; mt++) {
            int r = m0 + wm * 64 + mt * 16 + g;
            #pragma unroll
            for (int nt = 0; nt < 4; nt++) {
                int cc = n0 + wn * 32 + nt * 8 + t * 2;
                *(float2*)(C + (size_t)r * N + cc)       = make_float2(acc[mt][nt][0], acc[mt][nt][1]);
                *(float2*)(C + (size_t)(r + 8) * N + cc) = make_float2(acc[mt][nt][2], acc[mt][nt][3]);
            }
        }
    } else {
        const bool doRope = (MODE == 1) || !isV;
        #pragma unroll
        for (int mt = 0; mt < 4; mt++) {
            int r = m0 + wm * 64 + mt * 16 + g;
            int b = r >> 11;
            int sA = r & (S_ - 1);
            int sB = sA + 8;
            #pragma unroll
            for (int nt = 0; nt < 4; nt++) {
                int cc = n0 + wn * 32 + nt * 8 + t * 2;
                int h  = cc >> 7;
                int dd = cc & (D_ - 1);
                int p  = dd >> 1;

                float a0 = acc[mt][nt][0], a1 = acc[mt][nt][1];
                float a2 = acc[mt][nt][2], a3 = acc[mt][nt][3];
                float o0, o1, o2, o3;
                if (doRope) {
                    float2 csA = ((const float2*)fc)[(size_t)sA * 64 + p];
                    float2 csB = ((const float2*)fc)[(size_t)sB * 64 + p];
                    o0 = a0 * csA.x - a1 * csA.y;
                    o1 = a0 * csA.y + a1 * csA.x;
                    o2 = a2 * csB.x - a3 * csB.y;
                    o3 = a2 * csB.y + a3 * csB.x;
                } else {
                    o0 = a0; o1 = a1; o2 = a2; o3 = a3;
                }
                if (MODE == 1) { o0 *= SCALE_; o1 *= SCALE_; o2 *= SCALE_; o3 *= SCALE_; }

                uint2 u0 = make_uint2(f2tf32(o0), f2tf32(o1));
                uint2 u1 = make_uint2(f2tf32(o2), f2tf32(o3));

                if (MODE == 1) {
                    *(uint2*)(Ok + ((size_t)(b * HQ_ + h) * S_ + sA) * D_ + dd) = u0;
                    *(uint2*)(Ok + ((size_t)(b * HQ_ + h) * S_ + sB) * D_ + dd) = u1;
                } else {
                    int posA = ip[sA], posB = ip[sB];
                    uint32_t* Od = isV ? Ov : Ok;
                    *(uint2*)(Od + ((size_t)(b * HKV_ + h) * S_ + posA) * D_ + dd) = u0;
                    *(uint2*)(Od + ((size_t)(b * HKV_ + h) * S_ + posB) * D_ + dd) = u1;
                }
            }
        }
    }
}

// ---------------------------------------------------------------------------
// Fused flash attention (tf32 mma, unchanged math) — output now fp16 AO
// ---------------------------------------------------------------------------
#define FSTR 132

__device__ __forceinline__ void fa_load_kv(
    uint32_t* Ks, uint32_t* Vs, int stage,
    const uint32_t* __restrict__ Kp, const uint32_t* __restrict__ Vp, int tid)
{
    uint32_t* kd = Ks + stage * 64 * FSTR;
    uint32_t* vd = Vs + stage * 64 * FSTR;
    #pragma unroll
    for (int i = 0; i < 8; i++) {
        int e = i * 256 + tid;
        int r = e >> 5, c4 = (e & 31) * 4;
        cp16(kd + r * FSTR + c4, Kp + (size_t)r * D_ + c4);
        cp16(vd + r * FSTR + c4, Vp + (size_t)r * D_ + c4);
    }
}

__global__ __launch_bounds__(256, 1) void flash_tf32(
    const uint32_t* __restrict__ Qb, const uint32_t* __restrict__ Kc,
    const uint32_t* __restrict__ Vc, __half* __restrict__ AO)
{
    extern __shared__ uint32_t smbuf[];
    uint32_t* Qs = smbuf;
    uint32_t* Ks = smbuf + 128 * FSTR;
    uint32_t* Vs = smbuf + 128 * FSTR + 2 * 64 * FSTR;

    const int qt = (S_ / 128 - 1) - blockIdx.x;
    const int bh = blockIdx.y;
    const int b = bh / HQ_, h = bh % HQ_;
    const int kvh = h / (HQ_ / HKV_);
    const int m0 = qt * 128;

    const int tid = threadIdx.x, lane = tid & 31, warp = tid >> 5;
    const int g = lane >> 2, t = lane & 3;

    const uint32_t* Qbase = Qb + (size_t)(b * HQ_ + h) * S_ * D_ + (size_t)m0 * D_;
    const uint32_t* Kbase = Kc + (size_t)(b * HKV_ + kvh) * S_ * D_;
    const uint32_t* Vbase = Vc + (size_t)(b * HKV_ + kvh) * S_ * D_;

    #pragma unroll
    for (int i = 0; i < 16; i++) {
        int e = i * 256 + tid;
        int r = e >> 5, c4 = (e & 31) * 4;
        cp16(Qs + r * FSTR + c4, Qbase + (size_t)r * D_ + c4);
    }
    CP_COMMIT();

    const int nkt = 2 * qt + 2;
    fa_load_kv(Ks, Vs, 0, Kbase, Vbase, tid);
    CP_COMMIT();

    uint32_t qf[16][4];
    float Oacc[16][4] = {};
    float mrow0 = -FLT_MAX, mrow1 = -FLT_MAX;
    float lrow0 = 0.f, lrow1 = 0.f;

    const int srcA = (lane & ~3) | (t >> 1);
    const int srcB = srcA + 2;
    const bool odd = (t & 1);

    for (int kt = 0; kt < nkt; kt++) {
        const int s = kt & 1;
        if (kt + 1 < nkt) {
            fa_load_kv(Ks, Vs, s ^ 1, Kbase + (size_t)(kt + 1) * 64 * D_,
                       Vbase + (size_t)(kt + 1) * 64 * D_, tid);
            CP_COMMIT();
            CP_WAIT(1);
        } else {
            CP_WAIT(0);
        }
        __syncthreads();

        if (kt == 0) {
            #pragma unroll
            for (int ks = 0; ks < 16; ks++) {
                int r = warp * 16 + g, kc = ks * 8 + t;
                qf[ks][0] = Qs[r * FSTR + kc];
                qf[ks][1] = Qs[(r + 8) * FSTR + kc];
                qf[ks][2] = Qs[r * FSTR + kc + 4];
                qf[ks][3] = Qs[(r + 8) * FSTR + kc + 4];
            }
        }

        const uint32_t* ks_base = Ks + s * 64 * FSTR;
        const uint32_t* vs_base = Vs + s * 64 * FSTR;

        float sc[8][4];
        #pragma unroll
        for (int nf = 0; nf < 8; nf++)
            sc[nf][0] = sc[nf][1] = sc[nf][2] = sc[nf][3] = 0.f;
        #pragma unroll
        for (int ks = 0; ks < 16; ks++) {
            #pragma unroll
            for (int nf = 0; nf < 8; nf++) {
                uint32_t bb[2];
                const uint32_t* kp = ks_base + (nf * 8 + g) * FSTR + ks * 8 + t;
                bb[0] = kp[0];
                bb[1] = kp[4];
                mma_tf32(sc[nf], qf[ks], bb);
            }
        }

        const int r0 = m0 + warp * 16 + g;
        const int r1 = r0 + 8;
        if (kt >= 2 * qt) {
            #pragma unroll
            for (int nf = 0; nf < 8; nf++) {
                int c0 = kt * 64 + nf * 8 + 2 * t;
                if (c0     > r0) sc[nf][0] = -FLT_MAX;
                if (c0 + 1 > r0) sc[nf][1] = -FLT_MAX;
                if (c0     > r1) sc[nf][2] = -FLT_MAX;
                if (c0 + 1 > r1) sc[nf][3] = -FLT_MAX;
            }
        }

        float mx0 = -FLT_MAX, mx1 = -FLT_MAX;
        #pragma unroll
        for (int nf = 0; nf < 8; nf++) {
            mx0 = fmaxf(mx0, fmaxf(sc[nf][0], sc[nf][1]));
            mx1 = fmaxf(mx1, fmaxf(sc[nf][2], sc[nf][3]));
        }
        mx0 = fmaxf(mx0, __shfl_xor_sync(0xffffffffu, mx0, 1));
        mx0 = fmaxf(mx0, __shfl_xor_sync(0xffffffffu, mx0, 2));
        mx1 = fmaxf(mx1, __shfl_xor_sync(0xffffffffu, mx1, 1));
        mx1 = fmaxf(mx1, __shfl_xor_sync(0xffffffffu, mx1, 2));

        float mnew0 = fmaxf(mrow0, mx0), mnew1 = fmaxf(mrow1, mx1);
        float f0 = __expf(mrow0 - mnew0), f1 = __expf(mrow1 - mnew1);
        mrow0 = mnew0; mrow1 = mnew1;

        float rs0 = 0.f, rs1 = 0.f;
        #pragma unroll
        for (int nf = 0; nf < 8; nf++) {
            sc[nf][0] = __expf(sc[nf][0] - mnew0);
            sc[nf][1] = __expf(sc[nf][1] - mnew0);
            sc[nf][2] = __expf(sc[nf][2] - mnew1);
            sc[nf][3] = __expf(sc[nf][3] - mnew1);
            rs0 += sc[nf][0] + sc[nf][1];
            rs1 += sc[nf][2] + sc[nf][3];
        }
        rs0 += __shfl_xor_sync(0xffffffffu, rs0, 1);
        rs0 += __shfl_xor_sync(0xffffffffu, rs0, 2);
        rs1 += __shfl_xor_sync(0xffffffffu, rs1, 1);
        rs1 += __shfl_xor_sync(0xffffffffu, rs1, 2);
        lrow0 = lrow0 * f0 + rs0;
        lrow1 = lrow1 * f1 + rs1;

        #pragma unroll
        for (int nf2 = 0; nf2 < 16; nf2++) {
            Oacc[nf2][0] *= f0; Oacc[nf2][1] *= f0;
            Oacc[nf2][2] *= f1; Oacc[nf2][3] *= f1;
        }

        #pragma unroll
        for (int kc2 = 0; kc2 < 8; kc2++) {
            float vA0 = __shfl_sync(0xffffffffu, sc[kc2][0], srcA);
            float vA1 = __shfl_sync(0xffffffffu, sc[kc2][1], srcA);
            float vA2 = __shfl_sync(0xffffffffu, sc[kc2][2], srcA);
            float vA3 = __shfl_sync(0xffffffffu, sc[kc2][3], srcA);
            float vB0 = __shfl_sync(0xffffffffu, sc[kc2][0], srcB);
            float vB1 = __shfl_sync(0xffffffffu, sc[kc2][1], srcB);
            float vB2 = __shfl_sync(0xffffffffu, sc[kc2][2], srcB);
            float vB3 = __shfl_sync(0xffffffffu, sc[kc2][3], srcB);
            uint32_t aP[4];
            aP[0] = f2tf32(odd ? vA1 : vA0);
            aP[1] = f2tf32(odd ? vA3 : vA2);
            aP[2] = f2tf32(odd ? vB1 : vB0);
            aP[3] = f2tf32(odd ? vB3 : vB2);

            #pragma unroll
            for (int nf2 = 0; nf2 < 16; nf2++) {
                uint32_t bv[2];
                const uint32_t* vp = vs_base + (kc2 * 8 + t) * FSTR + nf2 * 8 + g;
                bv[0] = vp[0];
                bv[1] = vp[4 * FSTR];
                mma_tf32(Oacc[nf2], aP, bv);
            }
        }

        __syncthreads();
    }

    const float inv0 = 1.0f / lrow0, inv1 = 1.0f / lrow1;
    const int r0 = m0 + warp * 16 + g;
    #pragma unroll
    for (int nf2 = 0; nf2 < 16; nf2++) {
        int cc = h * D_ + nf2 * 8 + 2 * t;
        __half* C0 = AO + (size_t)(b * S_ + r0) * (HQ_ * D_) + cc;
        __half* C1 = AO + (size_t)(b * S_ + r0 + 8) * (HQ_ * D_) + cc;
        *(__half2*)C0 = __floats2half2_rn(Oacc[nf2][0] * inv0, Oacc[nf2][1] * inv0);
        *(__half2*)C1 = __floats2half2_rn(Oacc[nf2][2] * inv1, Oacc[nf2][3] * inv1);
    }
}

#define FLASH_SMEM ((128 * FSTR + 4 * 64 * FSTR) * 4)

// ---------------------------------------------------------------------------
// kernel_launch
// ---------------------------------------------------------------------------
extern "C" void kernel_launch(void* const* d_in, const int* in_sizes, int n_in,
                              void* d_out, int out_size) {
    const float* x  = (const float*)d_in[0];
    const int*   ip = (const int*)  d_in[1];
    const float* fc = (const float*)d_in[2];
    const float* wq = (const float*)d_in[3];
    const float* wk = (const float*)d_in[4];
    const float* wv = (const float*)d_in[5];
    const float* wo = (const float*)d_in[6];
    float* out = (float*)d_out;

    __half *xH, *wqT, *wkT, *wvT, *woT, *AO;
    uint32_t *Qb, *Kc, *Vc;
    cudaGetSymbolAddress((void**)&xH,  g_xH);
    cudaGetSymbolAddress((void**)&wqT, g_wqT);
    cudaGetSymbolAddress((void**)&wkT, g_wkT);
    cudaGetSymbolAddress((void**)&wvT, g_wvT);
    cudaGetSymbolAddress((void**)&woT, g_woT);
    cudaGetSymbolAddress((void**)&Qb,  g_Qb);
    cudaGetSymbolAddress((void**)&Kc,  g_Kc);
    cudaGetSymbolAddress((void**)&Vc,  g_Vc);
    cudaGetSymbolAddress((void**)&AO,  g_AO);

    static int attr_set = 0;
    if (!attr_set) {
        cudaFuncSetAttribute(flash_tf32, cudaFuncAttributeMaxDynamicSharedMemorySize, FLASH_SMEM);
        cudaFuncSetAttribute(gemm_f16<0>, cudaFuncAttributeMaxDynamicSharedMemorySize, GEMM_DSMEM);
        cudaFuncSetAttribute(gemm_f16<1>, cudaFuncAttributeMaxDynamicSharedMemorySize, GEMM_DSMEM);
        cudaFuncSetAttribute(gemm_f16<2>, cudaFuncAttributeMaxDynamicSharedMemorySize, GEMM_DSMEM);
        attr_set = 1;
    }

    // 0) pre-convert x (fp16), transpose+convert weights (fp16 [N][K])
    const int n4_x = (M_ * E_) / 4;
    cvt_f16_arr<<<(n4_x + 255) / 256, 256>>>((const float4*)x, (uint2*)xH, n4_x);
    cvt_transpose_h<<<dim3((HQ_ * D_) / 32, E_ / 32), dim3(32, 8)>>>(wq, wqT, E_, HQ_ * D_);
    cvt_transpose_h<<<dim3((HKV_ * D_) / 32, E_ / 32), dim3(32, 8)>>>(wk, wkT, E_, HKV_ * D_);
    cvt_transpose_h<<<dim3((HKV_ * D_) / 32, E_ / 32), dim3(32, 8)>>>(wv, wvT, E_, HKV_ * D_);
    cvt_transpose_h<<<dim3(E_ / 32, (HQ_ * D_) / 32), dim3(32, 8)>>>(wo, woT, HQ_ * D_, E_);

    // 1) Q projection (fp16 mma, RoPE+scale+transpose epilogue -> tf32 bits)
    gemm_f16<1><<<dim3((HQ_ * D_) / 128, M_ / 128), 256, GEMM_DSMEM>>>(
        xH, wqT, nullptr, nullptr, Qb, nullptr, fc, nullptr, M_, HQ_ * D_, E_);

    // 2) K+V projections (fp16 mma, RoPE/copy + cache scatter -> tf32 bits)
    gemm_f16<2><<<dim3(16, M_ / 128), 256, GEMM_DSMEM>>>(
        xH, wkT, wvT, nullptr, Kc, Vc, fc, ip, M_, HKV_ * D_, E_);

    // 3) Fused flash attention (tf32), writes fp16 AO
    flash_tf32<<<dim3(S_ / 128, B_ * HQ_), 256, FLASH_SMEM>>>(Qb, Kc, Vc, AO);

    // 4) Output projection (fp16 mma, fp32 out)
    gemm_f16<0><<<dim3(E_ / 128, M_ / 128), 256, GEMM_DSMEM>>>(
        AO, woT, nullptr, out, nullptr, nullptr, nullptr, nullptr, M_, E_, E_);
}

// round 9
// speedup vs baseline: 12.9168x; 1.3049x over previous
#include <cuda_runtime.h>
#include <cuda_fp16.h>
#include <float.h>
#include <math.h>
#include <stdint.h>

// Problem constants
#define B_   2
#define S_   2048
#define E_   4096
#define HQ_  32
#define HKV_ 8
#define D_   128
#define M_   (B_ * S_)          // 4096
#define SCALE_ 0.015625f        // 1/sqrt(4096)

// ---------------------------------------------------------------------------
// Scratch
// ---------------------------------------------------------------------------
__device__ __half g_xH [(size_t)M_ * E_];             // x fp16 [M][K]
__device__ __half g_wqT[(size_t)(HQ_ * D_) * E_];     // wq^T [N][K]
__device__ __half g_wkT[(size_t)(HKV_ * D_) * E_];    // wk^T
__device__ __half g_wvT[(size_t)(HKV_ * D_) * E_];    // wv^T
__device__ __half g_woT[(size_t)E_ * (HQ_ * D_)];     // wo^T
__device__ __half g_Qb [(size_t)B_ * HQ_ * S_ * D_];  // roped+scaled Q  [b,h,s,d]
__device__ __half g_Kc [(size_t)B_ * HKV_ * S_ * D_]; // roped K cache   [b,h,pos,d]
__device__ __half g_Vc [(size_t)B_ * HKV_ * D_ * S_]; // V cache TRANSPOSED [b,h,d,pos]
__device__ __half g_AO [(size_t)M_ * (HQ_ * D_)];     // attn out fp16

// ---------------------------------------------------------------------------
// helpers
// ---------------------------------------------------------------------------
__device__ __forceinline__ void mma_f16(float* c, const uint32_t* a, const uint32_t* b) {
    asm volatile(
        "mma.sync.aligned.m16n8k16.row.col.f32.f16.f16.f32 "
        "{%0,%1,%2,%3},{%4,%5,%6,%7},{%8,%9},{%0,%1,%2,%3};"
        : "+f"(c[0]), "+f"(c[1]), "+f"(c[2]), "+f"(c[3])
        : "r"(a[0]), "r"(a[1]), "r"(a[2]), "r"(a[3]), "r"(b[0]), "r"(b[1]));
}
__device__ __forceinline__ void cp16s(uint32_t saddr, const void* gmem) {
    asm volatile("cp.async.cg.shared.global [%0], [%1], 16;\n" :: "r"(saddr), "l"(gmem));
}
#define CP_COMMIT() asm volatile("cp.async.commit_group;\n" ::: "memory")
#define CP_WAIT(n)  asm volatile("cp.async.wait_group %0;\n" :: "n"(n) : "memory")
__device__ __forceinline__ uint32_t smem_u32(const void* p) {
    return (uint32_t)__cvta_generic_to_shared(p);
}
__device__ __forceinline__ uint32_t pack_h2(float a, float b) {
    __half2 h = __floats2half2_rn(a, b);
    return *(uint32_t*)&h;
}
__device__ __forceinline__ uint32_t lds32(uint32_t addr) {
    uint32_t v;
    asm volatile("ld.shared.b32 %0, [%1];" : "=r"(v) : "r"(addr));
    return v;
}
// swizzled byte offsets (cp = 16B-chunk index within row)
#define OFF256(row, cp) ((uint32_t)((row) * 256 + (((((cp) & 7) ^ ((row) & 7)) | ((cp) & 8)) << 4)))
#define OFF128(row, cp) ((uint32_t)((row) * 128 + ((((cp) ^ ((row) & 7))) << 4)))

// ---------------------------------------------------------------------------
// Pre-pass: fp32 -> fp16 (+ transpose for weights)
// ---------------------------------------------------------------------------
__global__ void cvt_f16_arr(const float4* __restrict__ in, uint2* __restrict__ out, int n4) {
    int i = blockIdx.x * 256 + threadIdx.x;
    if (i < n4) {
        float4 v = in[i];
        out[i] = make_uint2(pack_h2(v.x, v.y), pack_h2(v.z, v.w));
    }
}
__global__ void cvt_transpose_h(const float* __restrict__ in, __half* __restrict__ out,
                                int Kd, int Nd) {
    __shared__ __half t[32][33];
    int bx = blockIdx.x * 32, by = blockIdx.y * 32;
    int x = threadIdx.x, y = threadIdx.y;
    #pragma unroll
    for (int j = 0; j < 32; j += 8)
        t[y + j][x] = __float2half(in[(size_t)(by + y + j) * Nd + bx + x]);
    __syncthreads();
    #pragma unroll
    for (int j = 0; j < 32; j += 8)
        out[(size_t)(bx + y + j) * Kd + by + x] = t[x][y + j];
}

// ---------------------------------------------------------------------------
// fp16 GEMM (same core as R8). Epilogues now emit fp16.
//   MODE 0: fp32 C out (out-projection)
//   MODE 1: Q proj: RoPE + *SCALE_ + transpose -> Ok fp16 [b,h,s,d]
//   MODE 2: K/V proj: bx<8 K (RoPE+scatter) -> Ok [b,h,pos,d];
//           else V -> Ov TRANSPOSED [b,h,d,pos]
// ---------------------------------------------------------------------------
#define KCH 64
#define TILEB (128 * 128)
#define GEMM_DSMEM (4 * TILEB)

template<int MODE>
__global__ __launch_bounds__(256, 2) void gemm_f16(
    const __half* __restrict__ A, const __half* __restrict__ Btk,
    const __half* __restrict__ Btv,
    float* __restrict__ C, __half* __restrict__ Ok, __half* __restrict__ Ov,
    const float* __restrict__ fc, const int* __restrict__ ip,
    int M, int N, int K)
{
    extern __shared__ __align__(128) uint8_t dynraw[];
    const uint32_t smBase = smem_u32(dynraw);

    const int tid = threadIdx.x;
    const int lane = tid & 31, warp = tid >> 5;
    const int g = lane >> 2, t = lane & 3;
    const int wm = warp & 1, wn = warp >> 1;
    const int m0 = blockIdx.y * 128;

    const __half* Bt;
    int n0;
    bool isV = false;
    if (MODE == 2) {
        if (blockIdx.x < 8) { Bt = Btk; n0 = blockIdx.x * 128; }
        else                { Bt = Btv; n0 = (blockIdx.x - 8) * 128; isV = true; }
    } else {
        Bt = Btk; n0 = blockIdx.x * 128;
    }

    float acc[4][4][4] = {};

    auto load_chunk = [&](int ck, int st) {
        const uint32_t aB = smBase + st * TILEB;
        const uint32_t bB = smBase + 2 * TILEB + st * TILEB;
        #pragma unroll
        for (int i = 0; i < 4; i++) {
            int c = i * 256 + tid;
            int row = c >> 3, cp = c & 7;
            uint32_t off = (uint32_t)(row * 128 + ((cp ^ (row & 7)) << 4));
            cp16s(aB + off, A  + (size_t)(m0 + row) * K + ck * KCH + cp * 8);
            cp16s(bB + off, Bt + (size_t)(n0 + row) * K + ck * KCH + cp * 8);
        }
        CP_COMMIT();
    };

    const int nchunk = K / KCH;
    load_chunk(0, 0);

    for (int ci = 0; ci < nchunk; ci++) {
        const int s = ci & 1;
        if (ci + 1 < nchunk) {
            load_chunk(ci + 1, s ^ 1);
            CP_WAIT(1);
        } else {
            CP_WAIT(0);
        }
        __syncthreads();

        const uint32_t* A32 = (const uint32_t*)(dynraw + s * TILEB);
        const uint32_t* B32 = (const uint32_t*)(dynraw + 2 * TILEB + s * TILEB);

        #pragma unroll
        for (int kk = 0; kk < 4; kk++) {
            const int ch0 = ((2 * kk)     ^ g) << 2;
            const int ch1 = ((2 * kk + 1) ^ g) << 2;
            uint32_t af[4][4], bf[4][2];
            #pragma unroll
            for (int mt = 0; mt < 4; mt++) {
                int w = (wm * 64 + mt * 16 + g) * 32;
                af[mt][0] = A32[w + ch0 + t];
                af[mt][1] = A32[w + 256 + ch0 + t];
                af[mt][2] = A32[w + ch1 + t];
                af[mt][3] = A32[w + 256 + ch1 + t];
            }
            #pragma unroll
            for (int nt = 0; nt < 4; nt++) {
                int w = (wn * 32 + nt * 8 + g) * 32;
                bf[nt][0] = B32[w + ch0 + t];
                bf[nt][1] = B32[w + ch1 + t];
            }
            #pragma unroll
            for (int mt = 0; mt < 4; mt++)
                #pragma unroll
                for (int nt = 0; nt < 4; nt++)
                    mma_f16(acc[mt][nt], af[mt], bf[nt]);
        }
        __syncthreads();
    }

    if (MODE == 0) {
        #pragma unroll
        for (int mt = 0; mt < 4; mt++) {
            int r = m0 + wm * 64 + mt * 16 + g;
            #pragma unroll
            for (int nt = 0; nt < 4; nt++) {
                int cc = n0 + wn * 32 + nt * 8 + t * 2;
                *(float2*)(C + (size_t)r * N + cc)       = make_float2(acc[mt][nt][0], acc[mt][nt][1]);
                *(float2*)(C + (size_t)(r + 8) * N + cc) = make_float2(acc[mt][nt][2], acc[mt][nt][3]);
            }
        }
    } else {
        const bool doRope = (MODE == 1) || !isV;
        #pragma unroll
        for (int mt = 0; mt < 4; mt++) {
            int r = m0 + wm * 64 + mt * 16 + g;
            int b = r >> 11;
            int sA = r & (S_ - 1);
            int sB = sA + 8;
            #pragma unroll
            for (int nt = 0; nt < 4; nt++) {
                int cc = n0 + wn * 32 + nt * 8 + t * 2;
                int h  = cc >> 7;
                int dd = cc & (D_ - 1);
                int p  = dd >> 1;

                float a0 = acc[mt][nt][0], a1 = acc[mt][nt][1];
                float a2 = acc[mt][nt][2], a3 = acc[mt][nt][3];
                float o0, o1, o2, o3;
                if (doRope) {
                    float2 csA = ((const float2*)fc)[(size_t)sA * 64 + p];
                    float2 csB = ((const float2*)fc)[(size_t)sB * 64 + p];
                    o0 = a0 * csA.x - a1 * csA.y;
                    o1 = a0 * csA.y + a1 * csA.x;
                    o2 = a2 * csB.x - a3 * csB.y;
                    o3 = a2 * csB.y + a3 * csB.x;
                } else {
                    o0 = a0; o1 = a1; o2 = a2; o3 = a3;
                }
                if (MODE == 1) { o0 *= SCALE_; o1 *= SCALE_; o2 *= SCALE_; o3 *= SCALE_; }

                if (MODE == 1) {
                    __half2 u0 = __floats2half2_rn(o0, o1);
                    __half2 u1 = __floats2half2_rn(o2, o3);
                    *(__half2*)(Ok + ((size_t)(b * HQ_ + h) * S_ + sA) * D_ + dd) = u0;
                    *(__half2*)(Ok + ((size_t)(b * HQ_ + h) * S_ + sB) * D_ + dd) = u1;
                } else if (!isV) {
                    int posA = ip[sA], posB = ip[sB];
                    __half2 u0 = __floats2half2_rn(o0, o1);
                    __half2 u1 = __floats2half2_rn(o2, o3);
                    *(__half2*)(Ok + ((size_t)(b * HKV_ + h) * S_ + posA) * D_ + dd) = u0;
                    *(__half2*)(Ok + ((size_t)(b * HKV_ + h) * S_ + posB) * D_ + dd) = u1;
                } else {
                    // V transposed: [b,h,d,pos]
                    int posA = ip[sA], posB = ip[sB];
                    size_t base = (size_t)(b * HKV_ + h) * D_;
                    Ov[(base + dd)     * S_ + posA] = __float2half(o0);
                    Ov[(base + dd + 1) * S_ + posA] = __float2half(o1);
                    Ov[(base + dd)     * S_ + posB] = __float2half(o2);
                    Ov[(base + dd + 1) * S_ + posB] = __float2half(o3);
                }
            }
        }
    }
}

// ---------------------------------------------------------------------------
// Fused flash attention, fully fp16 mma. One block = one (b,h) x 128 Q rows.
// 8 warps x 16 rows. K tiles [64 keys][128 d] fp16; V^T tiles [128 d][64 keys].
// Swizzled smem; Q fragments register-resident; P relayout = register packing.
// ---------------------------------------------------------------------------
#define SMQ_OFF  0
#define SMK_OFF  32768
#define SMV_OFF  (32768 + 2 * 16384)
#define FLASH_SMEM (32768 + 4 * 16384)

__device__ __forceinline__ void fa_load_kv_h(
    uint32_t smBase, int stage,
    const __half* __restrict__ Kp,    // K rows base for this tile (key-major)
    const __half* __restrict__ Vtp,   // V^T base (d-major) for this head
    int kcol0, int tid)               // kcol0 = kt*64
{
    const uint32_t kB = smBase + SMK_OFF + stage * 16384;
    const uint32_t vB = smBase + SMV_OFF + stage * 16384;
    #pragma unroll
    for (int i = 0; i < 4; i++) {
        int c = i * 256 + tid;
        {   // K: 64 rows x 16 chunks
            int row = c >> 4, cp = c & 15;
            cp16s(kB + OFF256(row, cp), Kp + (size_t)row * D_ + cp * 8);
        }
        {   // V^T: 128 rows x 8 chunks
            int row = c >> 3, cp = c & 7;
            cp16s(vB + OFF128(row, cp), Vtp + (size_t)row * S_ + kcol0 + cp * 8);
        }
    }
    CP_COMMIT();
}

__global__ __launch_bounds__(256, 1) void flash_f16(
    const __half* __restrict__ Qb, const __half* __restrict__ Kc,
    const __half* __restrict__ Vc, __half* __restrict__ AO)
{
    extern __shared__ __align__(128) uint8_t smraw[];
    const uint32_t smBase = smem_u32(smraw);

    const int qt = (S_ / 128 - 1) - blockIdx.x;   // heavy tiles first
    const int bh = blockIdx.y;
    const int b = bh / HQ_, h = bh % HQ_;
    const int kvh = h / (HQ_ / HKV_);
    const int m0 = qt * 128;

    const int tid = threadIdx.x, lane = tid & 31, warp = tid >> 5;
    const int g = lane >> 2, t = lane & 3;

    const __half* Qbase = Qb + (size_t)(b * HQ_ + h) * S_ * D_ + (size_t)m0 * D_;
    const __half* Kbase = Kc + (size_t)(b * HKV_ + kvh) * S_ * D_;
    const __half* Vtb   = Vc + (size_t)(b * HKV_ + kvh) * D_ * S_;

    // stage Q tile: 128 rows x 16 chunks = 2048, 8/thread
    #pragma unroll
    for (int i = 0; i < 8; i++) {
        int c = i * 256 + tid;
        int row = c >> 4, cp = c & 15;
        cp16s(smBase + SMQ_OFF + OFF256(row, cp), Qbase + (size_t)row * D_ + cp * 8);
    }
    CP_COMMIT();

    const int nkt = 2 * qt + 2;
    fa_load_kv_h(smBase, 0, Kbase, Vtb, 0, tid);

    uint32_t qf[8][4];
    float Oacc[16][4] = {};
    float mrow0 = -FLT_MAX, mrow1 = -FLT_MAX;
    float lrow0 = 0.f, lrow1 = 0.f;

    for (int kt = 0; kt < nkt; kt++) {
        const int s = kt & 1;
        if (kt + 1 < nkt) {
            fa_load_kv_h(smBase, s ^ 1, Kbase + (size_t)(kt + 1) * 64 * D_,
                         Vtb, (kt + 1) * 64, tid);
            CP_WAIT(1);
        } else {
            CP_WAIT(0);
        }
        __syncthreads();

        if (kt == 0) {
            const int r = warp * 16 + g;
            #pragma unroll
            for (int ks = 0; ks < 8; ks++) {
                qf[ks][0] = lds32(smBase + SMQ_OFF + OFF256(r,     2 * ks)     + 4 * t);
                qf[ks][1] = lds32(smBase + SMQ_OFF + OFF256(r + 8, 2 * ks)     + 4 * t);
                qf[ks][2] = lds32(smBase + SMQ_OFF + OFF256(r,     2 * ks + 1) + 4 * t);
                qf[ks][3] = lds32(smBase + SMQ_OFF + OFF256(r + 8, 2 * ks + 1) + 4 * t);
            }
        }

        const uint32_t kB = smBase + SMK_OFF + s * 16384;
        const uint32_t vB = smBase + SMV_OFF + s * 16384;

        // ---- S = Q K^T : 8 k16-steps x 8 key-frags ----
        float sc[8][4];
        #pragma unroll
        for (int nf = 0; nf < 8; nf++)
            sc[nf][0] = sc[nf][1] = sc[nf][2] = sc[nf][3] = 0.f;
        #pragma unroll
        for (int ks = 0; ks < 8; ks++) {
            #pragma unroll
            for (int nf = 0; nf < 8; nf++) {
                const int j = nf * 8 + g;
                uint32_t bb[2];
                bb[0] = lds32(kB + OFF256(j, 2 * ks)     + 4 * t);
                bb[1] = lds32(kB + OFF256(j, 2 * ks + 1) + 4 * t);
                mma_f16(sc[nf], qf[ks], bb);
            }
        }

        // ---- causal mask (diagonal tiles only) ----
        const int r0 = m0 + warp * 16 + g;
        const int r1 = r0 + 8;
        if (kt >= 2 * qt) {
            #pragma unroll
            for (int nf = 0; nf < 8; nf++) {
                int c0 = kt * 64 + nf * 8 + 2 * t;
                if (c0     > r0) sc[nf][0] = -FLT_MAX;
                if (c0 + 1 > r0) sc[nf][1] = -FLT_MAX;
                if (c0     > r1) sc[nf][2] = -FLT_MAX;
                if (c0 + 1 > r1) sc[nf][3] = -FLT_MAX;
            }
        }

        // ---- online softmax ----
        float mx0 = -FLT_MAX, mx1 = -FLT_MAX;
        #pragma unroll
        for (int nf = 0; nf < 8; nf++) {
            mx0 = fmaxf(mx0, fmaxf(sc[nf][0], sc[nf][1]));
            mx1 = fmaxf(mx1, fmaxf(sc[nf][2], sc[nf][3]));
        }
        mx0 = fmaxf(mx0, __shfl_xor_sync(0xffffffffu, mx0, 1));
        mx0 = fmaxf(mx0, __shfl_xor_sync(0xffffffffu, mx0, 2));
        mx1 = fmaxf(mx1, __shfl_xor_sync(0xffffffffu, mx1, 1));
        mx1 = fmaxf(mx1, __shfl_xor_sync(0xffffffffu, mx1, 2));

        float mnew0 = fmaxf(mrow0, mx0), mnew1 = fmaxf(mrow1, mx1);
        float f0 = __expf(mrow0 - mnew0), f1 = __expf(mrow1 - mnew1);
        mrow0 = mnew0; mrow1 = mnew1;

        float rs0 = 0.f, rs1 = 0.f;
        #pragma unroll
        for (int nf = 0; nf < 8; nf++) {
            sc[nf][0] = __expf(sc[nf][0] - mnew0);
            sc[nf][1] = __expf(sc[nf][1] - mnew0);
            sc[nf][2] = __expf(sc[nf][2] - mnew1);
            sc[nf][3] = __expf(sc[nf][3] - mnew1);
            rs0 += sc[nf][0] + sc[nf][1];
            rs1 += sc[nf][2] + sc[nf][3];
        }
        rs0 += __shfl_xor_sync(0xffffffffu, rs0, 1);
        rs0 += __shfl_xor_sync(0xffffffffu, rs0, 2);
        rs1 += __shfl_xor_sync(0xffffffffu, rs1, 1);
        rs1 += __shfl_xor_sync(0xffffffffu, rs1, 2);
        lrow0 = lrow0 * f0 + rs0;
        lrow1 = lrow1 * f1 + rs1;

        #pragma unroll
        for (int nf2 = 0; nf2 < 16; nf2++) {
            Oacc[nf2][0] *= f0; Oacc[nf2][1] *= f0;
            Oacc[nf2][2] *= f1; Oacc[nf2][3] *= f1;
        }

        // ---- O += P V : A-frag = in-thread packing of sc pairs ----
        #pragma unroll
        for (int kk = 0; kk < 4; kk++) {
            uint32_t aP[4];
            aP[0] = pack_h2(sc[2 * kk][0],     sc[2 * kk][1]);
            aP[1] = pack_h2(sc[2 * kk][2],     sc[2 * kk][3]);
            aP[2] = pack_h2(sc[2 * kk + 1][0], sc[2 * kk + 1][1]);
            aP[3] = pack_h2(sc[2 * kk + 1][2], sc[2 * kk + 1][3]);

            #pragma unroll
            for (int nf2 = 0; nf2 < 16; nf2++) {
                const int dr = nf2 * 8 + g;
                uint32_t bv[2];
                bv[0] = lds32(vB + OFF128(dr, 2 * kk)     + 4 * t);
                bv[1] = lds32(vB + OFF128(dr, 2 * kk + 1) + 4 * t);
                mma_f16(Oacc[nf2], aP, bv);
            }
        }

        __syncthreads();
    }

    // ---- normalize + store fp16 (PV output cols = d rows of V^T) ----
    const float inv0 = 1.0f / lrow0, inv1 = 1.0f / lrow1;
    const int r0 = m0 + warp * 16 + g;
    #pragma unroll
    for (int nf2 = 0; nf2 < 16; nf2++) {
        int cc = h * D_ + nf2 * 8 + 2 * t;
        __half* C0 = AO + (size_t)(b * S_ + r0) * (HQ_ * D_) + cc;
        __half* C1 = AO + (size_t)(b * S_ + r0 + 8) * (HQ_ * D_) + cc;
        *(__half2*)C0 = __floats2half2_rn(Oacc[nf2][0] * inv0, Oacc[nf2][1] * inv0);
        *(__half2*)C1 = __floats2half2_rn(Oacc[nf2][2] * inv1, Oacc[nf2][3] * inv1);
    }
}

// ---------------------------------------------------------------------------
// kernel_launch
// ---------------------------------------------------------------------------
extern "C" void kernel_launch(void* const* d_in, const int* in_sizes, int n_in,
                              void* d_out, int out_size) {
    const float* x  = (const float*)d_in[0];
    const int*   ip = (const int*)  d_in[1];
    const float* fc = (const float*)d_in[2];
    const float* wq = (const float*)d_in[3];
    const float* wk = (const float*)d_in[4];
    const float* wv = (const float*)d_in[5];
    const float* wo = (const float*)d_in[6];
    float* out = (float*)d_out;

    __half *xH, *wqT, *wkT, *wvT, *woT, *Qb, *Kc, *Vc, *AO;
    cudaGetSymbolAddress((void**)&xH,  g_xH);
    cudaGetSymbolAddress((void**)&wqT, g_wqT);
    cudaGetSymbolAddress((void**)&wkT, g_wkT);
    cudaGetSymbolAddress((void**)&wvT, g_wvT);
    cudaGetSymbolAddress((void**)&woT, g_woT);
    cudaGetSymbolAddress((void**)&Qb,  g_Qb);
    cudaGetSymbolAddress((void**)&Kc,  g_Kc);
    cudaGetSymbolAddress((void**)&Vc,  g_Vc);
    cudaGetSymbolAddress((void**)&AO,  g_AO);

    static int attr_set = 0;
    if (!attr_set) {
        cudaFuncSetAttribute(flash_f16, cudaFuncAttributeMaxDynamicSharedMemorySize, FLASH_SMEM);
        cudaFuncSetAttribute(gemm_f16<0>, cudaFuncAttributeMaxDynamicSharedMemorySize, GEMM_DSMEM);
        cudaFuncSetAttribute(gemm_f16<1>, cudaFuncAttributeMaxDynamicSharedMemorySize, GEMM_DSMEM);
        cudaFuncSetAttribute(gemm_f16<2>, cudaFuncAttributeMaxDynamicSharedMemorySize, GEMM_DSMEM);
        attr_set = 1;
    }

    // 0) pre-convert x (fp16), transpose+convert weights (fp16 [N][K])
    const int n4_x = (M_ * E_) / 4;
    cvt_f16_arr<<<(n4_x + 255) / 256, 256>>>((const float4*)x, (uint2*)xH, n4_x);
    cvt_transpose_h<<<dim3((HQ_ * D_) / 32, E_ / 32), dim3(32, 8)>>>(wq, wqT, E_, HQ_ * D_);
    cvt_transpose_h<<<dim3((HKV_ * D_) / 32, E_ / 32), dim3(32, 8)>>>(wk, wkT, E_, HKV_ * D_);
    cvt_transpose_h<<<dim3((HKV_ * D_) / 32, E_ / 32), dim3(32, 8)>>>(wv, wvT, E_, HKV_ * D_);
    cvt_transpose_h<<<dim3(E_ / 32, (HQ_ * D_) / 32), dim3(32, 8)>>>(wo, woT, HQ_ * D_, E_);

    // 1) Q projection (fp16, RoPE+scale+transpose -> fp16 Qb)
    gemm_f16<1><<<dim3((HQ_ * D_) / 128, M_ / 128), 256, GEMM_DSMEM>>>(
        xH, wqT, nullptr, nullptr, Qb, nullptr, fc, nullptr, M_, HQ_ * D_, E_);

    // 2) K+V projections (fp16; K -> [pos,d], V -> transposed [d,pos])
    gemm_f16<2><<<dim3(16, M_ / 128), 256, GEMM_DSMEM>>>(
        xH, wkT, wvT, nullptr, Kc, Vc, fc, ip, M_, HKV_ * D_, E_);

    // 3) Fused flash attention (fp16 end-to-end)
    flash_f16<<<dim3(S_ / 128, B_ * HQ_), 256, FLASH_SMEM>>>(Qb, Kc, Vc, AO);

    // 4) Output projection (fp16 mma, fp32 out)
    gemm_f16<0><<<dim3(E_ / 128, M_ / 128), 256, GEMM_DSMEM>>>(
        AO, woT, nullptr, out, nullptr, nullptr, nullptr, nullptr, M_, E_, E_);
}

// round 10
// speedup vs baseline: 14.3594x; 1.1117x over previous
#include <cuda_runtime.h>
#include <cuda_fp16.h>
#include <float.h>
#include <math.h>
#include <stdint.h>

// Problem constants
#define B_   2
#define S_   2048
#define E_   4096
#define HQ_  32
#define HKV_ 8
#define D_   128
#define M_   (B_ * S_)          // 4096
#define SCALE_ 0.015625f        // 1/sqrt(4096)

// ---------------------------------------------------------------------------
// Scratch
// ---------------------------------------------------------------------------
__device__ __half g_xH [(size_t)M_ * E_];             // x fp16 [M][K]
__device__ __half g_wqT[(size_t)(HQ_ * D_) * E_];     // wq^T [N][K]
__device__ __half g_wkT[(size_t)(HKV_ * D_) * E_];    // wk^T
__device__ __half g_wvT[(size_t)(HKV_ * D_) * E_];    // wv^T
__device__ __half g_woT[(size_t)E_ * (HQ_ * D_)];     // wo^T
__device__ __half g_Qb [(size_t)B_ * HQ_ * S_ * D_];  // roped+scaled Q  [b,h,s,d]
__device__ __half g_Kc [(size_t)B_ * HKV_ * S_ * D_]; // roped K cache   [b,h,pos,d]
__device__ __half g_Vc [(size_t)B_ * HKV_ * D_ * S_]; // V cache transposed [b,h,d,pos]
__device__ __half g_AO [(size_t)M_ * (HQ_ * D_)];     // attn out fp16

// ---------------------------------------------------------------------------
// helpers
// ---------------------------------------------------------------------------
__device__ __forceinline__ void mma_f16(float* c, const uint32_t* a, const uint32_t* b) {
    asm volatile(
        "mma.sync.aligned.m16n8k16.row.col.f32.f16.f16.f32 "
        "{%0,%1,%2,%3},{%4,%5,%6,%7},{%8,%9},{%0,%1,%2,%3};"
        : "+f"(c[0]), "+f"(c[1]), "+f"(c[2]), "+f"(c[3])
        : "r"(a[0]), "r"(a[1]), "r"(a[2]), "r"(a[3]), "r"(b[0]), "r"(b[1]));
}
__device__ __forceinline__ void ldsm_x4(uint32_t* r, uint32_t addr) {
    asm volatile("ldmatrix.sync.aligned.m8n8.x4.shared.b16 {%0,%1,%2,%3}, [%4];"
        : "=r"(r[0]), "=r"(r[1]), "=r"(r[2]), "=r"(r[3]) : "r"(addr));
}
__device__ __forceinline__ void cp16s(uint32_t saddr, const void* gmem) {
    asm volatile("cp.async.cg.shared.global [%0], [%1], 16;\n" :: "r"(saddr), "l"(gmem));
}
#define CP_COMMIT() asm volatile("cp.async.commit_group;\n" ::: "memory")
#define CP_WAIT(n)  asm volatile("cp.async.wait_group %0;\n" :: "n"(n) : "memory")
__device__ __forceinline__ uint32_t smem_u32(const void* p) {
    return (uint32_t)__cvta_generic_to_shared(p);
}
__device__ __forceinline__ uint32_t pack_h2(float a, float b) {
    __half2 h = __floats2half2_rn(a, b);
    return *(uint32_t*)&h;
}
__device__ __forceinline__ uint32_t lds32(uint32_t addr) {
    uint32_t v;
    asm volatile("ld.shared.b32 %0, [%1];" : "=r"(v) : "r"(addr));
    return v;
}
// swizzled byte offsets (cp = 16B-chunk index within row)
#define OFF256(row, cp) ((uint32_t)((row) * 256 + (((((cp) & 7) ^ ((row) & 7)) | ((cp) & 8)) << 4)))
#define OFF128(row, cp) ((uint32_t)((row) * 128 + ((((cp) ^ ((row) & 7))) << 4)))

// ---------------------------------------------------------------------------
// Pre-pass: fp32 -> fp16 (+ transpose for weights)
// ---------------------------------------------------------------------------
__global__ void cvt_f16_arr(const float4* __restrict__ in, uint2* __restrict__ out, int n4) {
    int i = blockIdx.x * 256 + threadIdx.x;
    if (i < n4) {
        float4 v = in[i];
        out[i] = make_uint2(pack_h2(v.x, v.y), pack_h2(v.z, v.w));
    }
}
__global__ void cvt_transpose_h(const float* __restrict__ in, __half* __restrict__ out,
                                int Kd, int Nd) {
    __shared__ __half t[32][33];
    int bx = blockIdx.x * 32, by = blockIdx.y * 32;
    int x = threadIdx.x, y = threadIdx.y;
    #pragma unroll
    for (int j = 0; j < 32; j += 8)
        t[y + j][x] = __float2half(in[(size_t)(by + y + j) * Nd + bx + x]);
    __syncthreads();
    #pragma unroll
    for (int j = 0; j < 32; j += 8)
        out[(size_t)(bx + y + j) * Kd + by + x] = t[x][y + j];
}

// ---------------------------------------------------------------------------
// fp16 GEMM, ldmatrix fragment loads. 128x128 tile, KC=64, double-buffered.
//   MODE 0: fp32 C out (out-projection)
//   MODE 1: Q proj: RoPE + *SCALE_ + transpose -> Ok fp16 [b,h,s,d]
//   MODE 2: K/V proj: bx<8 K (RoPE+scatter) -> Ok [b,h,pos,d]; else V -> Ov [b,h,d,pos]
// ---------------------------------------------------------------------------
#define KCH 64
#define TILEB (128 * 128)
#define GEMM_DSMEM (4 * TILEB)

template<int MODE>
__global__ __launch_bounds__(256, 2) void gemm_f16(
    const __half* __restrict__ A, const __half* __restrict__ Btk,
    const __half* __restrict__ Btv,
    float* __restrict__ C, __half* __restrict__ Ok, __half* __restrict__ Ov,
    const float* __restrict__ fc, const int* __restrict__ ip,
    int M, int N, int K)
{
    extern __shared__ __align__(128) uint8_t dynraw[];
    const uint32_t smBase = smem_u32(dynraw);

    const int tid = threadIdx.x;
    const int lane = tid & 31, warp = tid >> 5;
    const int g = lane >> 2, t = lane & 3;
    const int wm = warp & 1, wn = warp >> 1;
    const int m0 = blockIdx.y * 128;

    // ldmatrix lane decomposition
    const int l7 = lane & 7, l15 = lane & 15;
    const int lhi = lane >> 4, lb3 = (lane >> 3) & 1;

    const __half* Bt;
    int n0;
    bool isV = false;
    if (MODE == 2) {
        if (blockIdx.x < 8) { Bt = Btk; n0 = blockIdx.x * 128; }
        else                { Bt = Btv; n0 = (blockIdx.x - 8) * 128; isV = true; }
    } else {
        Bt = Btk; n0 = blockIdx.x * 128;
    }

    float acc[4][4][4] = {};

    auto load_chunk = [&](int ck, int st) {
        const uint32_t aB = smBase + st * TILEB;
        const uint32_t bB = smBase + 2 * TILEB + st * TILEB;
        #pragma unroll
        for (int i = 0; i < 4; i++) {
            int c = i * 256 + tid;
            int row = c >> 3, cp = c & 7;
            uint32_t off = (uint32_t)(row * 128 + ((cp ^ (row & 7)) << 4));
            cp16s(aB + off, A  + (size_t)(m0 + row) * K + ck * KCH + cp * 8);
            cp16s(bB + off, Bt + (size_t)(n0 + row) * K + ck * KCH + cp * 8);
        }
        CP_COMMIT();
    };

    const int nchunk = K / KCH;
    load_chunk(0, 0);

    for (int ci = 0; ci < nchunk; ci++) {
        const int s = ci & 1;
        if (ci + 1 < nchunk) {
            load_chunk(ci + 1, s ^ 1);
            CP_WAIT(1);
        } else {
            CP_WAIT(0);
        }
        __syncthreads();

        const uint32_t aB = smBase + s * TILEB;
        const uint32_t bB = smBase + 2 * TILEB + s * TILEB;

        #pragma unroll
        for (int kk = 0; kk < 4; kk++) {
            uint32_t af[4][4], bf[2][4];
            // A: 4 ldmatrix.x4; matrices {m0c0, m8c0, m0c1, m8c1}
            #pragma unroll
            for (int mt = 0; mt < 4; mt++) {
                int row = wm * 64 + mt * 16 + l15;
                int ch  = 2 * kk + lhi;
                ldsm_x4(af[mt], aB + (uint32_t)(row * 128 + (((ch) ^ (row & 7)) << 4)));
            }
            // B: 2 ldmatrix.x4; matrices {nt0c0, nt0c1, nt1c0, nt1c1}
            #pragma unroll
            for (int p = 0; p < 2; p++) {
                int row = wn * 32 + p * 16 + lhi * 8 + l7;
                int ch  = 2 * kk + lb3;
                ldsm_x4(bf[p], bB + (uint32_t)(row * 128 + (((ch) ^ (row & 7)) << 4)));
            }
            #pragma unroll
            for (int mt = 0; mt < 4; mt++) {
                #pragma unroll
                for (int p = 0; p < 2; p++) {
                    mma_f16(acc[mt][2 * p],     af[mt], &bf[p][0]);
                    mma_f16(acc[mt][2 * p + 1], af[mt], &bf[p][2]);
                }
            }
        }
        __syncthreads();
    }

    if (MODE == 0) {
        #pragma unroll
        for (int mt = 0; mt < 4; mt++) {
            int r = m0 + wm * 64 + mt * 16 + g;
            #pragma unroll
            for (int nt = 0; nt < 4; nt++) {
                int cc = n0 + wn * 32 + nt * 8 + t * 2;
                *(float2*)(C + (size_t)r * N + cc)       = make_float2(acc[mt][nt][0], acc[mt][nt][1]);
                *(float2*)(C + (size_t)(r + 8) * N + cc) = make_float2(acc[mt][nt][2], acc[mt][nt][3]);
            }
        }
    } else {
        const bool doRope = (MODE == 1) || !isV;
        #pragma unroll
        for (int mt = 0; mt < 4; mt++) {
            int r = m0 + wm * 64 + mt * 16 + g;
            int b = r >> 11;
            int sA = r & (S_ - 1);
            int sB = sA + 8;
            #pragma unroll
            for (int nt = 0; nt < 4; nt++) {
                int cc = n0 + wn * 32 + nt * 8 + t * 2;
                int h  = cc >> 7;
                int dd = cc & (D_ - 1);
                int p  = dd >> 1;

                float a0 = acc[mt][nt][0], a1 = acc[mt][nt][1];
                float a2 = acc[mt][nt][2], a3 = acc[mt][nt][3];
                float o0, o1, o2, o3;
                if (doRope) {
                    float2 csA = ((const float2*)fc)[(size_t)sA * 64 + p];
                    float2 csB = ((const float2*)fc)[(size_t)sB * 64 + p];
                    o0 = a0 * csA.x - a1 * csA.y;
                    o1 = a0 * csA.y + a1 * csA.x;
                    o2 = a2 * csB.x - a3 * csB.y;
                    o3 = a2 * csB.y + a3 * csB.x;
                } else {
                    o0 = a0; o1 = a1; o2 = a2; o3 = a3;
                }
                if (MODE == 1) { o0 *= SCALE_; o1 *= SCALE_; o2 *= SCALE_; o3 *= SCALE_; }

                if (MODE == 1) {
                    *(__half2*)(Ok + ((size_t)(b * HQ_ + h) * S_ + sA) * D_ + dd) = __floats2half2_rn(o0, o1);
                    *(__half2*)(Ok + ((size_t)(b * HQ_ + h) * S_ + sB) * D_ + dd) = __floats2half2_rn(o2, o3);
                } else if (!isV) {
                    int posA = ip[sA], posB = ip[sB];
                    *(__half2*)(Ok + ((size_t)(b * HKV_ + h) * S_ + posA) * D_ + dd) = __floats2half2_rn(o0, o1);
                    *(__half2*)(Ok + ((size_t)(b * HKV_ + h) * S_ + posB) * D_ + dd) = __floats2half2_rn(o2, o3);
                } else {
                    int posA = ip[sA], posB = ip[sB];
                    size_t base = (size_t)(b * HKV_ + h) * D_;
                    Ov[(base + dd)     * S_ + posA] = __float2half(o0);
                    Ov[(base + dd + 1) * S_ + posA] = __float2half(o1);
                    Ov[(base + dd)     * S_ + posB] = __float2half(o2);
                    Ov[(base + dd + 1) * S_ + posB] = __float2half(o3);
                }
            }
        }
    }
}

// ---------------------------------------------------------------------------
// Fused flash attention, fp16 end-to-end, ldmatrix K/V fragment loads.
// ---------------------------------------------------------------------------
#define SMQ_OFF  0
#define SMK_OFF  32768
#define SMV_OFF  (32768 + 2 * 16384)
#define FLASH_SMEM (32768 + 4 * 16384)

__device__ __forceinline__ void fa_load_kv_h(
    uint32_t smBase, int stage,
    const __half* __restrict__ Kp, const __half* __restrict__ Vtp,
    int kcol0, int tid)
{
    const uint32_t kB = smBase + SMK_OFF + stage * 16384;
    const uint32_t vB = smBase + SMV_OFF + stage * 16384;
    #pragma unroll
    for (int i = 0; i < 4; i++) {
        int c = i * 256 + tid;
        {   // K: 64 rows x 16 chunks
            int row = c >> 4, cp = c & 15;
            cp16s(kB + OFF256(row, cp), Kp + (size_t)row * D_ + cp * 8);
        }
        {   // V^T: 128 rows x 8 chunks
            int row = c >> 3, cp = c & 7;
            cp16s(vB + OFF128(row, cp), Vtp + (size_t)row * S_ + kcol0 + cp * 8);
        }
    }
    CP_COMMIT();
}

__global__ __launch_bounds__(256, 1) void flash_f16(
    const __half* __restrict__ Qb, const __half* __restrict__ Kc,
    const __half* __restrict__ Vc, __half* __restrict__ AO)
{
    extern __shared__ __align__(128) uint8_t smraw[];
    const uint32_t smBase = smem_u32(smraw);

    const int qt = (S_ / 128 - 1) - blockIdx.x;
    const int bh = blockIdx.y;
    const int b = bh / HQ_, h = bh % HQ_;
    const int kvh = h / (HQ_ / HKV_);
    const int m0 = qt * 128;

    const int tid = threadIdx.x, lane = tid & 31, warp = tid >> 5;
    const int g = lane >> 2, t = lane & 3;
    const int l7 = lane & 7, lhi = lane >> 4, lb3 = (lane >> 3) & 1;

    const __half* Qbase = Qb + (size_t)(b * HQ_ + h) * S_ * D_ + (size_t)m0 * D_;
    const __half* Kbase = Kc + (size_t)(b * HKV_ + kvh) * S_ * D_;
    const __half* Vtb   = Vc + (size_t)(b * HKV_ + kvh) * D_ * S_;

    #pragma unroll
    for (int i = 0; i < 8; i++) {
        int c = i * 256 + tid;
        int row = c >> 4, cp = c & 15;
        cp16s(smBase + SMQ_OFF + OFF256(row, cp), Qbase + (size_t)row * D_ + cp * 8);
    }
    CP_COMMIT();

    const int nkt = 2 * qt + 2;
    fa_load_kv_h(smBase, 0, Kbase, Vtb, 0, tid);

    uint32_t qf[8][4];
    float Oacc[16][4] = {};
    float mrow0 = -FLT_MAX, mrow1 = -FLT_MAX;
    float lrow0 = 0.f, lrow1 = 0.f;

    for (int kt = 0; kt < nkt; kt++) {
        const int s = kt & 1;
        if (kt + 1 < nkt) {
            fa_load_kv_h(smBase, s ^ 1, Kbase + (size_t)(kt + 1) * 64 * D_,
                         Vtb, (kt + 1) * 64, tid);
            CP_WAIT(1);
        } else {
            CP_WAIT(0);
        }
        __syncthreads();

        if (kt == 0) {
            // Q fragments via ldmatrix: rows warp*16 + l15, chunks 2ks + lhi
            const int qrow = warp * 16 + (lane & 15);
            #pragma unroll
            for (int ks = 0; ks < 8; ks++) {
                int ch = 2 * ks + lhi;
                ldsm_x4(qf[ks], smBase + SMQ_OFF + OFF256(qrow, ch));
            }
        }

        const uint32_t kB = smBase + SMK_OFF + s * 16384;
        const uint32_t vB = smBase + SMV_OFF + s * 16384;

        // ---- S = Q K^T ----
        float sc[8][4];
        #pragma unroll
        for (int nf = 0; nf < 8; nf++)
            sc[nf][0] = sc[nf][1] = sc[nf][2] = sc[nf][3] = 0.f;
        #pragma unroll
        for (int ks = 0; ks < 8; ks++) {
            #pragma unroll
            for (int nfp = 0; nfp < 4; nfp++) {
                int krow = nfp * 16 + lhi * 8 + l7;
                int ch   = 2 * ks + lb3;
                uint32_t bb[4];
                ldsm_x4(bb, kB + OFF256(krow, ch));
                mma_f16(sc[2 * nfp],     qf[ks], &bb[0]);
                mma_f16(sc[2 * nfp + 1], qf[ks], &bb[2]);
            }
        }

        // ---- causal mask (diagonal tiles only) ----
        const int r0 = m0 + warp * 16 + g;
        const int r1 = r0 + 8;
        if (kt >= 2 * qt) {
            #pragma unroll
            for (int nf = 0; nf < 8; nf++) {
                int c0 = kt * 64 + nf * 8 + 2 * t;
                if (c0     > r0) sc[nf][0] = -FLT_MAX;
                if (c0 + 1 > r0) sc[nf][1] = -FLT_MAX;
                if (c0     > r1) sc[nf][2] = -FLT_MAX;
                if (c0 + 1 > r1) sc[nf][3] = -FLT_MAX;
            }
        }

        // ---- online softmax ----
        float mx0 = -FLT_MAX, mx1 = -FLT_MAX;
        #pragma unroll
        for (int nf = 0; nf < 8; nf++) {
            mx0 = fmaxf(mx0, fmaxf(sc[nf][0], sc[nf][1]));
            mx1 = fmaxf(mx1, fmaxf(sc[nf][2], sc[nf][3]));
        }
        mx0 = fmaxf(mx0, __shfl_xor_sync(0xffffffffu, mx0, 1));
        mx0 = fmaxf(mx0, __shfl_xor_sync(0xffffffffu, mx0, 2));
        mx1 = fmaxf(mx1, __shfl_xor_sync(0xffffffffu, mx1, 1));
        mx1 = fmaxf(mx1, __shfl_xor_sync(0xffffffffu, mx1, 2));

        float mnew0 = fmaxf(mrow0, mx0), mnew1 = fmaxf(mrow1, mx1);
        float f0 = __expf(mrow0 - mnew0), f1 = __expf(mrow1 - mnew1);
        mrow0 = mnew0; mrow1 = mnew1;

        float rs0 = 0.f, rs1 = 0.f;
        #pragma unroll
        for (int nf = 0; nf < 8; nf++) {
            sc[nf][0] = __expf(sc[nf][0] - mnew0);
            sc[nf][1] = __expf(sc[nf][1] - mnew0);
            sc[nf][2] = __expf(sc[nf][2] - mnew1);
            sc[nf][3] = __expf(sc[nf][3] - mnew1);
            rs0 += sc[nf][0] + sc[nf][1];
            rs1 += sc[nf][2] + sc[nf][3];
        }
        rs0 += __shfl_xor_sync(0xffffffffu, rs0, 1);
        rs0 += __shfl_xor_sync(0xffffffffu, rs0, 2);
        rs1 += __shfl_xor_sync(0xffffffffu, rs1, 1);
        rs1 += __shfl_xor_sync(0xffffffffu, rs1, 2);
        lrow0 = lrow0 * f0 + rs0;
        lrow1 = lrow1 * f1 + rs1;

        #pragma unroll
        for (int nf2 = 0; nf2 < 16; nf2++) {
            Oacc[nf2][0] *= f0; Oacc[nf2][1] *= f0;
            Oacc[nf2][2] *= f1; Oacc[nf2][3] *= f1;
        }

        // ---- O += P V ----
        #pragma unroll
        for (int kk = 0; kk < 4; kk++) {
            uint32_t aP[4];
            aP[0] = pack_h2(sc[2 * kk][0],     sc[2 * kk][1]);
            aP[1] = pack_h2(sc[2 * kk][2],     sc[2 * kk][3]);
            aP[2] = pack_h2(sc[2 * kk + 1][0], sc[2 * kk + 1][1]);
            aP[3] = pack_h2(sc[2 * kk + 1][2], sc[2 * kk + 1][3]);

            #pragma unroll
            for (int np = 0; np < 8; np++) {
                int vrow = np * 16 + lhi * 8 + l7;
                int ch   = 2 * kk + lb3;
                uint32_t bv4[4];
                ldsm_x4(bv4, vB + OFF128(vrow, ch));
                mma_f16(Oacc[2 * np],     aP, &bv4[0]);
                mma_f16(Oacc[2 * np + 1], aP, &bv4[2]);
            }
        }

        __syncthreads();
    }

    // ---- normalize + store fp16 ----
    const float inv0 = 1.0f / lrow0, inv1 = 1.0f / lrow1;
    const int r0 = m0 + warp * 16 + g;
    #pragma unroll
    for (int nf2 = 0; nf2 < 16; nf2++) {
        int cc = h * D_ + nf2 * 8 + 2 * t;
        __half* C0 = AO + (size_t)(b * S_ + r0) * (HQ_ * D_) + cc;
        __half* C1 = AO + (size_t)(b * S_ + r0 + 8) * (HQ_ * D_) + cc;
        *(__half2*)C0 = __floats2half2_rn(Oacc[nf2][0] * inv0, Oacc[nf2][1] * inv0);
        *(__half2*)C1 = __floats2half2_rn(Oacc[nf2][2] * inv1, Oacc[nf2][3] * inv1);
    }
}

// ---------------------------------------------------------------------------
// kernel_launch
// ---------------------------------------------------------------------------
extern "C" void kernel_launch(void* const* d_in, const int* in_sizes, int n_in,
                              void* d_out, int out_size) {
    const float* x  = (const float*)d_in[0];
    const int*   ip = (const int*)  d_in[1];
    const float* fc = (const float*)d_in[2];
    const float* wq = (const float*)d_in[3];
    const float* wk = (const float*)d_in[4];
    const float* wv = (const float*)d_in[5];
    const float* wo = (const float*)d_in[6];
    float* out = (float*)d_out;

    __half *xH, *wqT, *wkT, *wvT, *woT, *Qb, *Kc, *Vc, *AO;
    cudaGetSymbolAddress((void**)&xH,  g_xH);
    cudaGetSymbolAddress((void**)&wqT, g_wqT);
    cudaGetSymbolAddress((void**)&wkT, g_wkT);
    cudaGetSymbolAddress((void**)&wvT, g_wvT);
    cudaGetSymbolAddress((void**)&woT, g_woT);
    cudaGetSymbolAddress((void**)&Qb,  g_Qb);
    cudaGetSymbolAddress((void**)&Kc,  g_Kc);
    cudaGetSymbolAddress((void**)&Vc,  g_Vc);
    cudaGetSymbolAddress((void**)&AO,  g_AO);

    static int attr_set = 0;
    if (!attr_set) {
        cudaFuncSetAttribute(flash_f16, cudaFuncAttributeMaxDynamicSharedMemorySize, FLASH_SMEM);
        cudaFuncSetAttribute(gemm_f16<0>, cudaFuncAttributeMaxDynamicSharedMemorySize, GEMM_DSMEM);
        cudaFuncSetAttribute(gemm_f16<1>, cudaFuncAttributeMaxDynamicSharedMemorySize, GEMM_DSMEM);
        cudaFuncSetAttribute(gemm_f16<2>, cudaFuncAttributeMaxDynamicSharedMemorySize, GEMM_DSMEM);
        attr_set = 1;
    }

    // 0) pre-convert x (fp16), transpose+convert weights (fp16 [N][K])
    const int n4_x = (M_ * E_) / 4;
    cvt_f16_arr<<<(n4_x + 255) / 256, 256>>>((const float4*)x, (uint2*)xH, n4_x);
    cvt_transpose_h<<<dim3((HQ_ * D_) / 32, E_ / 32), dim3(32, 8)>>>(wq, wqT, E_, HQ_ * D_);
    cvt_transpose_h<<<dim3((HKV_ * D_) / 32, E_ / 32), dim3(32, 8)>>>(wk, wkT, E_, HKV_ * D_);
    cvt_transpose_h<<<dim3((HKV_ * D_) / 32, E_ / 32), dim3(32, 8)>>>(wv, wvT, E_, HKV_ * D_);
    cvt_transpose_h<<<dim3(E_ / 32, (HQ_ * D_) / 32), dim3(32, 8)>>>(wo, woT, HQ_ * D_, E_);

    // 1) Q projection (fp16, RoPE+scale+transpose -> fp16 Qb)
    gemm_f16<1><<<dim3((HQ_ * D_) / 128, M_ / 128), 256, GEMM_DSMEM>>>(
        xH, wqT, nullptr, nullptr, Qb, nullptr, fc, nullptr, M_, HQ_ * D_, E_);

    // 2) K+V projections (fp16; K -> [pos,d], V -> transposed [d,pos])
    gemm_f16<2><<<dim3(16, M_ / 128), 256, GEMM_DSMEM>>>(
        xH, wkT, wvT, nullptr, Kc, Vc, fc, ip, M_, HKV_ * D_, E_);

    // 3) Fused flash attention (fp16, ldmatrix)
    flash_f16<<<dim3(S_ / 128, B_ * HQ_), 256, FLASH_SMEM>>>(Qb, Kc, Vc, AO);

    // 4) Output projection (fp16 mma, fp32 out)
    gemm_f16<0><<<dim3(E_ / 128, M_ / 128), 256, GEMM_DSMEM>>>(
        AO, woT, nullptr, out, nullptr, nullptr, nullptr, nullptr, M_, E_, E_);
}